// round 1
// baseline (speedup 1.0000x reference)
#include <cuda_runtime.h>

// Problem dims (fixed for this dataset)
#define BDIM 4096   // batch rows of x
#define PDIM 512    // prototypes
#define IDIM 1024   // inner dim
#define FDIM 2048   // features

// Tiling
#define BM 64
#define BN 64
#define BK 16
#define SMS 68      // smem row stride in floats (16B-aligned, kills most bank conflicts)

// Scratch: device globals (allocation-free rule)
__device__ float g_a [BDIM * FDIM];   // xf * relu(xf)
__device__ float g_xp[BDIM * FDIM];   // relu(xf)
__device__ float g_c [PDIM * FDIM];   // pf * relu(pf)
__device__ float g_pp[PDIM * FDIM];   // relu(pf)

// ---------------------------------------------------------------------------
// Stage 1: Y = In @ Feat^T   (In: [R, IDIM], Feat: [FDIM, IDIM], both K-major)
// writes  outSq = relu(y)*y  and  outPres = relu(y)
// mode 0 -> x path (g_a, g_xp), mode 1 -> prototype path (g_c, g_pp)
// ---------------------------------------------------------------------------
__global__ __launch_bounds__(256, 2)
void stage1_kernel(const float* __restrict__ In, const float* __restrict__ Feat, int mode)
{
    __shared__ float As[BK][SMS];
    __shared__ float Bs[BK][SMS];

    const int tid  = threadIdx.x;
    const int row0 = blockIdx.y * BM;
    const int col0 = blockIdx.x * BN;

    // loader: each thread fetches one float4 per tile per operand
    const int ldRow = tid >> 2;          // 0..63
    const int ldK   = (tid & 3) << 2;    // 0,4,8,12

    // compute: 16x16 thread grid, 4x4 per thread
    const int ty = tid >> 4;
    const int tx = tid & 15;

    float* outSq   = mode ? g_c  : g_a;
    float* outPres = mode ? g_pp : g_xp;

    const float* aPtr = In   + (size_t)(row0 + ldRow) * IDIM + ldK;
    const float* bPtr = Feat + (size_t)(col0 + ldRow) * IDIM + ldK;

    float acc[4][4];
#pragma unroll
    for (int m = 0; m < 4; m++)
#pragma unroll
        for (int n = 0; n < 4; n++) acc[m][n] = 0.f;

    float4 av = *(const float4*)(aPtr);
    float4 bv = *(const float4*)(bPtr);

    for (int k0 = 0; k0 < IDIM; k0 += BK) {
        // stage to smem transposed (k-major) for conflict-free LDS.128 reads
        As[ldK + 0][ldRow] = av.x; As[ldK + 1][ldRow] = av.y;
        As[ldK + 2][ldRow] = av.z; As[ldK + 3][ldRow] = av.w;
        Bs[ldK + 0][ldRow] = bv.x; Bs[ldK + 1][ldRow] = bv.y;
        Bs[ldK + 2][ldRow] = bv.z; Bs[ldK + 3][ldRow] = bv.w;
        __syncthreads();

        if (k0 + BK < IDIM) {           // register prefetch of next tile
            av = *(const float4*)(aPtr + k0 + BK);
            bv = *(const float4*)(bPtr + k0 + BK);
        }

#pragma unroll
        for (int k = 0; k < BK; k++) {
            float4 a4 = *(const float4*)&As[k][ty << 2];
            float4 b4 = *(const float4*)&Bs[k][tx << 2];
            float am[4] = {a4.x, a4.y, a4.z, a4.w};
            float bn[4] = {b4.x, b4.y, b4.z, b4.w};
#pragma unroll
            for (int m = 0; m < 4; m++)
#pragma unroll
                for (int n = 0; n < 4; n++)
                    acc[m][n] += am[m] * bn[n];
        }
        __syncthreads();
    }

    // epilogue: a = relu(y)*y, pres = relu(y); vectorized stores
#pragma unroll
    for (int m = 0; m < 4; m++) {
        const size_t r = (size_t)(row0 + (ty << 2) + m);
        float4 pvec, svec;
        float y, p;
        y = acc[m][0]; p = y > 0.f ? y : 0.f; pvec.x = p; svec.x = p * y;
        y = acc[m][1]; p = y > 0.f ? y : 0.f; pvec.y = p; svec.y = p * y;
        y = acc[m][2]; p = y > 0.f ? y : 0.f; pvec.z = p; svec.z = p * y;
        y = acc[m][3]; p = y > 0.f ? y : 0.f; pvec.w = p; svec.w = p * y;
        const size_t off = r * FDIM + col0 + (tx << 2);
        *(float4*)&outPres[off] = pvec;
        *(float4*)&outSq[off]   = svec;
    }
}

// ---------------------------------------------------------------------------
// Stage 2: fused triple contraction over F
//   d1 = a@c.T, d2 = a@pp.T, d3 = xp@c.T, sumA = rowsum(a), sumC = rowsum(c)
//   out = theta*d1 - alpha*(sumA - d2) - beta*(sumC - d3)
// ---------------------------------------------------------------------------
__global__ __launch_bounds__(256, 2)
void stage2_kernel(const float* __restrict__ alpha, const float* __restrict__ beta,
                   const float* __restrict__ theta, float* __restrict__ Out)
{
    __shared__ float sA[BK][SMS];
    __shared__ float sX[BK][SMS];
    __shared__ float sC[BK][SMS];
    __shared__ float sP[BK][SMS];

    const int tid  = threadIdx.x;
    const int row0 = blockIdx.y * BM;   // batch tile
    const int col0 = blockIdx.x * BN;   // prototype tile

    const int ldRow = tid >> 2;
    const int ldK   = (tid & 3) << 2;
    const int ty = tid >> 4;
    const int tx = tid & 15;

    const float* aP = g_a  + (size_t)(row0 + ldRow) * FDIM + ldK;
    const float* xP = g_xp + (size_t)(row0 + ldRow) * FDIM + ldK;
    const float* cP = g_c  + (size_t)(col0 + ldRow) * FDIM + ldK;
    const float* pP = g_pp + (size_t)(col0 + ldRow) * FDIM + ldK;

    float d1[4][4], d2[4][4], d3[4][4];
#pragma unroll
    for (int m = 0; m < 4; m++)
#pragma unroll
        for (int n = 0; n < 4; n++) { d1[m][n] = 0.f; d2[m][n] = 0.f; d3[m][n] = 0.f; }
    float sumA[4] = {0.f, 0.f, 0.f, 0.f};
    float sumC[4] = {0.f, 0.f, 0.f, 0.f};

    float4 av = *(const float4*)aP;
    float4 xv = *(const float4*)xP;
    float4 cv = *(const float4*)cP;
    float4 pv = *(const float4*)pP;

    for (int k0 = 0; k0 < FDIM; k0 += BK) {
        sA[ldK + 0][ldRow] = av.x; sA[ldK + 1][ldRow] = av.y;
        sA[ldK + 2][ldRow] = av.z; sA[ldK + 3][ldRow] = av.w;
        sX[ldK + 0][ldRow] = xv.x; sX[ldK + 1][ldRow] = xv.y;
        sX[ldK + 2][ldRow] = xv.z; sX[ldK + 3][ldRow] = xv.w;
        sC[ldK + 0][ldRow] = cv.x; sC[ldK + 1][ldRow] = cv.y;
        sC[ldK + 2][ldRow] = cv.z; sC[ldK + 3][ldRow] = cv.w;
        sP[ldK + 0][ldRow] = pv.x; sP[ldK + 1][ldRow] = pv.y;
        sP[ldK + 2][ldRow] = pv.z; sP[ldK + 3][ldRow] = pv.w;
        __syncthreads();

        if (k0 + BK < FDIM) {
            av = *(const float4*)(aP + k0 + BK);
            xv = *(const float4*)(xP + k0 + BK);
            cv = *(const float4*)(cP + k0 + BK);
            pv = *(const float4*)(pP + k0 + BK);
        }

#pragma unroll
        for (int k = 0; k < BK; k++) {
            float4 a4 = *(const float4*)&sA[k][ty << 2];
            float4 x4 = *(const float4*)&sX[k][ty << 2];
            float4 c4 = *(const float4*)&sC[k][tx << 2];
            float4 p4 = *(const float4*)&sP[k][tx << 2];
            float am[4] = {a4.x, a4.y, a4.z, a4.w};
            float xm[4] = {x4.x, x4.y, x4.z, x4.w};
            float cn[4] = {c4.x, c4.y, c4.z, c4.w};
            float pn[4] = {p4.x, p4.y, p4.z, p4.w};
#pragma unroll
            for (int m = 0; m < 4; m++) sumA[m] += am[m];
#pragma unroll
            for (int n = 0; n < 4; n++) sumC[n] += cn[n];
#pragma unroll
            for (int m = 0; m < 4; m++)
#pragma unroll
                for (int n = 0; n < 4; n++) {
                    d1[m][n] += am[m] * cn[n];
                    d2[m][n] += am[m] * pn[n];
                    d3[m][n] += xm[m] * cn[n];
                }
        }
        __syncthreads();
    }

    const float al = __ldg(alpha);
    const float be = __ldg(beta);
    const float th = __ldg(theta);

#pragma unroll
    for (int m = 0; m < 4; m++) {
        const size_t r = (size_t)(row0 + (ty << 2) + m);
        float4 o;
        o.x = th * d1[m][0] - al * (sumA[m] - d2[m][0]) - be * (sumC[0] - d3[m][0]);
        o.y = th * d1[m][1] - al * (sumA[m] - d2[m][1]) - be * (sumC[1] - d3[m][1]);
        o.z = th * d1[m][2] - al * (sumA[m] - d2[m][2]) - be * (sumC[2] - d3[m][2]);
        o.w = th * d1[m][3] - al * (sumA[m] - d2[m][3]) - be * (sumC[3] - d3[m][3]);
        *(float4*)&Out[r * PDIM + col0 + (tx << 2)] = o;
    }
}

// ---------------------------------------------------------------------------
extern "C" void kernel_launch(void* const* d_in, const int* in_sizes, int n_in,
                              void* d_out, int out_size)
{
    const float* x     = (const float*)d_in[0];  // [4096, 1024]
    const float* feat  = (const float*)d_in[1];  // [2048, 1024]
    const float* proto = (const float*)d_in[2];  // [512, 1024]
    const float* alpha = (const float*)d_in[3];
    const float* beta  = (const float*)d_in[4];
    const float* theta = (const float*)d_in[5];
    float* out = (float*)d_out;                  // [4096, 512]

    dim3 blk(256);
    stage1_kernel<<<dim3(FDIM / BN, BDIM / BM), blk>>>(x,     feat, 0);
    stage1_kernel<<<dim3(FDIM / BN, PDIM / BM), blk>>>(proto, feat, 1);
    stage2_kernel<<<dim3(PDIM / BN, BDIM / BM), blk>>>(alpha, beta, theta, out);
}

// round 3
// speedup vs baseline: 2.7146x; 2.7146x over previous
#include <cuda_runtime.h>
#include <stdint.h>

#define BDIM 4096
#define PDIM 512
#define IDIM 1024
#define FDIM 2048

#define PAD 20          // floats per 16-float smem row (bank-conflict-free for frag loads)
#define STAGES 3

// ---------------- scratch (device globals; allocation-free rule) ----------------
__device__ __align__(128) float g_x[(size_t)BDIM * IDIM];  // tf32-rounded x
__device__ __align__(128) float g_f[(size_t)FDIM * IDIM];  // tf32-rounded features
__device__ __align__(128) float g_p[(size_t)PDIM * IDIM];  // tf32-rounded prototypes
__device__ __align__(128) float g_a[(size_t)BDIM * FDIM];  // tf32( xf * relu(xf) )
__device__ __align__(128) float g_r[(size_t)BDIM * FDIM];  // tf32( 1 - relu(xf) )
__device__ __align__(128) float g_c[(size_t)PDIM * FDIM];  // tf32( pf * relu(pf) )
__device__ __align__(128) float g_q[(size_t)PDIM * FDIM];  // tf32( 1 - relu(pf) )

// ---------------- helpers ----------------
__device__ __forceinline__ uint32_t f2tf(float f) {
    uint32_t r; asm("cvt.rna.tf32.f32 %0, %1;" : "=r"(r) : "f"(f)); return r;
}
__device__ __forceinline__ float tfr(float f) { return __uint_as_float(f2tf(f)); }

__device__ __forceinline__ uint32_t s2u(const void* p) {
    uint32_t a;
    asm("{ .reg .u64 t; cvta.to.shared.u64 t, %1; cvt.u32.u64 %0, t; }" : "=r"(a) : "l"(p));
    return a;
}

#define CP16(dst, src) \
    asm volatile("cp.async.cg.shared.global [%0], [%1], 16;" :: "r"(dst), "l"(src))
#define CPCOMMIT() asm volatile("cp.async.commit_group;")
#define CPWAIT1()  asm volatile("cp.async.wait_group 1;")

__device__ __forceinline__ void mma8(float c[4], const uint32_t a[4], const uint32_t b[2]) {
    asm volatile(
        "mma.sync.aligned.m16n8k8.row.col.f32.tf32.tf32.f32 "
        "{%0,%1,%2,%3}, {%4,%5,%6,%7}, {%8,%9}, {%0,%1,%2,%3};"
        : "+f"(c[0]), "+f"(c[1]), "+f"(c[2]), "+f"(c[3])
        : "r"(a[0]), "r"(a[1]), "r"(a[2]), "r"(a[3]), "r"(b[0]), "r"(b[1]));
}

// ---------------- tf32 rounding pass ----------------
__global__ void round_kernel(const float* __restrict__ in, float* __restrict__ out, int n4)
{
    int i = blockIdx.x * blockDim.x + threadIdx.x;
    if (i < n4) {
        float4 v = ((const float4*)in)[i];
        v.x = tfr(v.x); v.y = tfr(v.y); v.z = tfr(v.z); v.w = tfr(v.w);
        ((float4*)out)[i] = v;
    }
}

// =================================================================
// Stage 1:  Y = In @ Feat^T  (both K-major, K=1024)
//   outSq = tf32( y * relu(y) ), outInv = tf32( 1 - relu(y) )
// CTA tile 128x128x16, 8 warps (2x4), warp tile 64x32, 3-stage cp.async
// =================================================================
#define S1_STRIDE (2 * 128 * PAD)             // floats per stage
#define S1_SMEM   (STAGES * S1_STRIDE * 4)    // bytes

__global__ __launch_bounds__(256)
void s1_kernel(const float* __restrict__ In, const float* __restrict__ Feat,
               float* __restrict__ outSq, float* __restrict__ outInv)
{
    extern __shared__ float sm1[];
    const int tid = threadIdx.x;
    const int wid = tid >> 5, lid = tid & 31;
    const int g = lid >> 2, tg = lid & 3;
    const int wm = wid >> 2, wn = wid & 3;          // 2 x 4 warp grid
    const int row0 = blockIdx.y * 128, col0 = blockIdx.x * 128;

    const float* gA = In   + (size_t)row0 * IDIM;
    const float* gB = Feat + (size_t)col0 * IDIM;

    float acc[4][4][4];
#pragma unroll
    for (int mi = 0; mi < 4; mi++)
#pragma unroll
        for (int ni = 0; ni < 4; ni++)
#pragma unroll
            for (int j = 0; j < 4; j++) acc[mi][ni][j] = 0.f;

    const int NIT = IDIM / 16;   // 64

    // prologue
#pragma unroll
    for (int s = 0; s < STAGES - 1; s++) {
        float* As = sm1 + s * S1_STRIDE;
        float* Bs = As + 128 * PAD;
        const int k0 = s * 16;
#pragma unroll
        for (int i = 0; i < 2; i++) {
            int idx = tid + i * 256;            // 0..511
            int row = idx >> 2, ch = idx & 3;
            CP16(s2u(As + row * PAD + ch * 4), gA + (size_t)row * IDIM + k0 + ch * 4);
            CP16(s2u(Bs + row * PAD + ch * 4), gB + (size_t)row * IDIM + k0 + ch * 4);
        }
        CPCOMMIT();
    }

    for (int it = 0; it < NIT; it++) {
        CPWAIT1();
        __syncthreads();

        const int nxt = it + STAGES - 1;
        if (nxt < NIT) {
            float* As = sm1 + (nxt % STAGES) * S1_STRIDE;
            float* Bs = As + 128 * PAD;
            const int k0 = nxt * 16;
#pragma unroll
            for (int i = 0; i < 2; i++) {
                int idx = tid + i * 256;
                int row = idx >> 2, ch = idx & 3;
                CP16(s2u(As + row * PAD + ch * 4), gA + (size_t)row * IDIM + k0 + ch * 4);
                CP16(s2u(Bs + row * PAD + ch * 4), gB + (size_t)row * IDIM + k0 + ch * 4);
            }
        }
        CPCOMMIT();

        const float* As = sm1 + (it % STAGES) * S1_STRIDE;
        const float* Bs = As + 128 * PAD;
#pragma unroll
        for (int ks = 0; ks < 2; ks++) {
            const int kk = ks * 8;
            uint32_t af[4][4], bf[4][2];
#pragma unroll
            for (int mi = 0; mi < 4; mi++) {
                const int r = wm * 64 + mi * 16 + g;
                af[mi][0] = __float_as_uint(As[r * PAD + kk + tg]);
                af[mi][1] = __float_as_uint(As[(r + 8) * PAD + kk + tg]);
                af[mi][2] = __float_as_uint(As[r * PAD + kk + tg + 4]);
                af[mi][3] = __float_as_uint(As[(r + 8) * PAD + kk + tg + 4]);
            }
#pragma unroll
            for (int ni = 0; ni < 4; ni++) {
                const int c = wn * 32 + ni * 8 + g;
                bf[ni][0] = __float_as_uint(Bs[c * PAD + kk + tg]);
                bf[ni][1] = __float_as_uint(Bs[c * PAD + kk + tg + 4]);
            }
#pragma unroll
            for (int mi = 0; mi < 4; mi++)
#pragma unroll
                for (int ni = 0; ni < 4; ni++)
                    mma8(acc[mi][ni], af[mi], bf[ni]);
        }
        __syncthreads();
    }

    // epilogue
#pragma unroll
    for (int mi = 0; mi < 4; mi++)
#pragma unroll
        for (int ni = 0; ni < 4; ni++) {
            const int rr = row0 + wm * 64 + mi * 16 + g;
            const int cc = col0 + wn * 32 + ni * 8 + tg * 2;
#pragma unroll
            for (int h = 0; h < 2; h++) {
                const float y0 = acc[mi][ni][h * 2 + 0];
                const float y1 = acc[mi][ni][h * 2 + 1];
                const float p0 = fmaxf(y0, 0.f), p1 = fmaxf(y1, 0.f);
                float2 sv = { tfr(y0 * p0), tfr(y1 * p1) };
                float2 iv = { tfr(1.f - p0), tfr(1.f - p1) };
                const size_t off = (size_t)(rr + h * 8) * FDIM + cc;
                *(float2*)&outSq[off]  = sv;
                *(float2*)&outInv[off] = iv;
            }
        }
}

// =================================================================
// Stage 2: D1 = a@c^T, D2 = a@q^T, D3 = r@c^T  over F=2048
//          out = theta*D1 - alpha*D2 - beta*D3
// CTA tile 128x64x16, 8 warps (4x2), warp tile 32x32, 3 accumulators
// =================================================================
#define S2_STRIDE (2 * 128 * PAD + 2 * 64 * PAD)   // a, r, c, q
#define S2_SMEM   (STAGES * S2_STRIDE * 4)

__global__ __launch_bounds__(256)
void s2_kernel(const float* __restrict__ alpha, const float* __restrict__ beta,
               const float* __restrict__ theta, float* __restrict__ Out)
{
    extern __shared__ float sm2[];
    const int tid = threadIdx.x;
    const int wid = tid >> 5, lid = tid & 31;
    const int g = lid >> 2, tg = lid & 3;
    const int wm = wid >> 1, wn = wid & 1;          // 4 x 2 warp grid
    const int row0 = blockIdx.y * 128, col0 = blockIdx.x * 64;

    const float* gA = g_a + (size_t)row0 * FDIM;
    const float* gR = g_r + (size_t)row0 * FDIM;
    const float* gC = g_c + (size_t)col0 * FDIM;
    const float* gQ = g_q + (size_t)col0 * FDIM;

    float a1[2][4][4], a2[2][4][4], a3[2][4][4];
#pragma unroll
    for (int mi = 0; mi < 2; mi++)
#pragma unroll
        for (int ni = 0; ni < 4; ni++)
#pragma unroll
            for (int j = 0; j < 4; j++) { a1[mi][ni][j] = 0.f; a2[mi][ni][j] = 0.f; a3[mi][ni][j] = 0.f; }

    const int NIT = FDIM / 16;   // 128

#pragma unroll
    for (int s = 0; s < STAGES - 1; s++) {
        float* Sa = sm2 + s * S2_STRIDE;
        float* Sr = Sa + 128 * PAD;
        float* Sc = Sr + 128 * PAD;
        float* Sq = Sc + 64 * PAD;
        const int k0 = s * 16;
#pragma unroll
        for (int i = 0; i < 2; i++) {
            int idx = tid + i * 256;
            int row = idx >> 2, ch = idx & 3;
            CP16(s2u(Sa + row * PAD + ch * 4), gA + (size_t)row * FDIM + k0 + ch * 4);
            CP16(s2u(Sr + row * PAD + ch * 4), gR + (size_t)row * FDIM + k0 + ch * 4);
        }
        { int row = tid >> 2, ch = tid & 3;
          CP16(s2u(Sc + row * PAD + ch * 4), gC + (size_t)row * FDIM + k0 + ch * 4);
          CP16(s2u(Sq + row * PAD + ch * 4), gQ + (size_t)row * FDIM + k0 + ch * 4); }
        CPCOMMIT();
    }

    for (int it = 0; it < NIT; it++) {
        CPWAIT1();
        __syncthreads();

        const int nxt = it + STAGES - 1;
        if (nxt < NIT) {
            float* Sa = sm2 + (nxt % STAGES) * S2_STRIDE;
            float* Sr = Sa + 128 * PAD;
            float* Sc = Sr + 128 * PAD;
            float* Sq = Sc + 64 * PAD;
            const int k0 = nxt * 16;
#pragma unroll
            for (int i = 0; i < 2; i++) {
                int idx = tid + i * 256;
                int row = idx >> 2, ch = idx & 3;
                CP16(s2u(Sa + row * PAD + ch * 4), gA + (size_t)row * FDIM + k0 + ch * 4);
                CP16(s2u(Sr + row * PAD + ch * 4), gR + (size_t)row * FDIM + k0 + ch * 4);
            }
            { int row = tid >> 2, ch = tid & 3;
              CP16(s2u(Sc + row * PAD + ch * 4), gC + (size_t)row * FDIM + k0 + ch * 4);
              CP16(s2u(Sq + row * PAD + ch * 4), gQ + (size_t)row * FDIM + k0 + ch * 4); }
        }
        CPCOMMIT();

        const float* Sa = sm2 + (it % STAGES) * S2_STRIDE;
        const float* Sr = Sa + 128 * PAD;
        const float* Sc = Sr + 128 * PAD;
        const float* Sq = Sc + 64 * PAD;
#pragma unroll
        for (int ks = 0; ks < 2; ks++) {
            const int kk = ks * 8;
            uint32_t af[2][4], rf[2][4], bc[4][2], bq[4][2];
#pragma unroll
            for (int mi = 0; mi < 2; mi++) {
                const int r = wm * 32 + mi * 16 + g;
                af[mi][0] = __float_as_uint(Sa[r * PAD + kk + tg]);
                af[mi][1] = __float_as_uint(Sa[(r + 8) * PAD + kk + tg]);
                af[mi][2] = __float_as_uint(Sa[r * PAD + kk + tg + 4]);
                af[mi][3] = __float_as_uint(Sa[(r + 8) * PAD + kk + tg + 4]);
                rf[mi][0] = __float_as_uint(Sr[r * PAD + kk + tg]);
                rf[mi][1] = __float_as_uint(Sr[(r + 8) * PAD + kk + tg]);
                rf[mi][2] = __float_as_uint(Sr[r * PAD + kk + tg + 4]);
                rf[mi][3] = __float_as_uint(Sr[(r + 8) * PAD + kk + tg + 4]);
            }
#pragma unroll
            for (int ni = 0; ni < 4; ni++) {
                const int c = wn * 32 + ni * 8 + g;
                bc[ni][0] = __float_as_uint(Sc[c * PAD + kk + tg]);
                bc[ni][1] = __float_as_uint(Sc[c * PAD + kk + tg + 4]);
                bq[ni][0] = __float_as_uint(Sq[c * PAD + kk + tg]);
                bq[ni][1] = __float_as_uint(Sq[c * PAD + kk + tg + 4]);
            }
#pragma unroll
            for (int mi = 0; mi < 2; mi++)
#pragma unroll
                for (int ni = 0; ni < 4; ni++) {
                    mma8(a1[mi][ni], af[mi], bc[ni]);
                    mma8(a2[mi][ni], af[mi], bq[ni]);
                    mma8(a3[mi][ni], rf[mi], bc[ni]);
                }
        }
        __syncthreads();
    }

    const float al = __ldg(alpha);
    const float be = __ldg(beta);
    const float th = __ldg(theta);

#pragma unroll
    for (int mi = 0; mi < 2; mi++)
#pragma unroll
        for (int ni = 0; ni < 4; ni++) {
            const int rr = row0 + wm * 32 + mi * 16 + g;
            const int cc = col0 + wn * 32 + ni * 8 + tg * 2;
#pragma unroll
            for (int h = 0; h < 2; h++) {
                float2 o;
                o.x = th * a1[mi][ni][h * 2 + 0] - al * a2[mi][ni][h * 2 + 0] - be * a3[mi][ni][h * 2 + 0];
                o.y = th * a1[mi][ni][h * 2 + 1] - al * a2[mi][ni][h * 2 + 1] - be * a3[mi][ni][h * 2 + 1];
                *(float2*)&Out[(size_t)(rr + h * 8) * PDIM + cc] = o;
            }
        }
}

// ---------------- launch ----------------
extern "C" void kernel_launch(void* const* d_in, const int* in_sizes, int n_in,
                              void* d_out, int out_size)
{
    const float* x     = (const float*)d_in[0];
    const float* feat  = (const float*)d_in[1];
    const float* proto = (const float*)d_in[2];
    const float* alpha = (const float*)d_in[3];
    const float* beta  = (const float*)d_in[4];
    const float* theta = (const float*)d_in[5];
    float* out = (float*)d_out;

    float *dx, *df, *dp;
    cudaGetSymbolAddress((void**)&dx, g_x);
    cudaGetSymbolAddress((void**)&df, g_f);
    cudaGetSymbolAddress((void**)&dp, g_p);
    float *da, *dr, *dc, *dq;
    cudaGetSymbolAddress((void**)&da, g_a);
    cudaGetSymbolAddress((void**)&dr, g_r);
    cudaGetSymbolAddress((void**)&dc, g_c);
    cudaGetSymbolAddress((void**)&dq, g_q);

    static bool attr_done = false;
    if (!attr_done) {
        cudaFuncSetAttribute(s1_kernel, cudaFuncAttributeMaxDynamicSharedMemorySize, S1_SMEM);
        cudaFuncSetAttribute(s2_kernel, cudaFuncAttributeMaxDynamicSharedMemorySize, S2_SMEM);
        attr_done = true;
    }

    // tf32 pre-rounding (RN, zero-bias)
    round_kernel<<<(BDIM * IDIM / 4 + 255) / 256, 256>>>(x, dx, BDIM * IDIM / 4);
    round_kernel<<<(FDIM * IDIM / 4 + 255) / 256, 256>>>(feat, df, FDIM * IDIM / 4);
    round_kernel<<<(PDIM * IDIM / 4 + 255) / 256, 256>>>(proto, dp, PDIM * IDIM / 4);

    s1_kernel<<<dim3(FDIM / 128, BDIM / 128), 256, S1_SMEM>>>(dx, df, da, dr);
    s1_kernel<<<dim3(FDIM / 128, PDIM / 128), 256, S1_SMEM>>>(dp, df, dc, dq);
    s2_kernel<<<dim3(PDIM / 64, BDIM / 128), 256, S2_SMEM>>>(alpha, beta, theta, out);
}

// round 4
// speedup vs baseline: 3.2079x; 1.1817x over previous
#include <cuda_runtime.h>
#include <stdint.h>

#define BDIM 4096
#define PDIM 512
#define IDIM 1024
#define FDIM 2048

#define PAD 20          // floats per 16-float smem row
#define STAGES1 4       // s1 pipeline depth
#define STAGES2 3       // s2 pipeline depth

// ---------------- scratch (device globals; allocation-free rule) ----------------
__device__ __align__(128) float g_a[(size_t)BDIM * FDIM];  // tf32( xf * relu(xf) )
__device__ __align__(128) float g_r[(size_t)BDIM * FDIM];  // tf32( 1 - relu(xf) )
__device__ __align__(128) float g_c[(size_t)PDIM * FDIM];  // tf32( pf * relu(pf) )
__device__ __align__(128) float g_q[(size_t)PDIM * FDIM];  // tf32( 1 - relu(pf) )

// ---------------- helpers ----------------
__device__ __forceinline__ uint32_t f2tf(float f) {
    uint32_t r; asm("cvt.rna.tf32.f32 %0, %1;" : "=r"(r) : "f"(f)); return r;
}
__device__ __forceinline__ float tfr(float f) { return __uint_as_float(f2tf(f)); }

__device__ __forceinline__ uint32_t s2u(const void* p) {
    uint32_t a;
    asm("{ .reg .u64 t; cvta.to.shared.u64 t, %1; cvt.u32.u64 %0, t; }" : "=r"(a) : "l"(p));
    return a;
}

#define CP16(dst, src) \
    asm volatile("cp.async.cg.shared.global [%0], [%1], 16;" :: "r"(dst), "l"(src))
#define CPCOMMIT() asm volatile("cp.async.commit_group;")
#define CPWAIT(n)  asm volatile("cp.async.wait_group %0;" :: "n"(n))

__device__ __forceinline__ void mma8(float c[4], const uint32_t a[4], const uint32_t b[2]) {
    asm volatile(
        "mma.sync.aligned.m16n8k8.row.col.f32.tf32.tf32.f32 "
        "{%0,%1,%2,%3}, {%4,%5,%6,%7}, {%8,%9}, {%0,%1,%2,%3};"
        : "+f"(c[0]), "+f"(c[1]), "+f"(c[2]), "+f"(c[3])
        : "r"(a[0]), "r"(a[1]), "r"(a[2]), "r"(a[3]), "r"(b[0]), "r"(b[1]));
}

// =================================================================
// Stage 1 (merged): Y = In @ Feat^T for BOTH x (row-blocks 0..31) and
// prototypes (row-blocks 32..35).  cvt.rna.tf32 applied on fragment load.
//   outSq = tf32( y * relu(y) ), outInv = tf32( 1 - relu(y) )
// CTA tile 128x128x16, 8 warps (2x4), warp tile 64x32
// =================================================================
#define S1_STRIDE (2 * 128 * PAD)
#define S1_SMEM   (STAGES1 * S1_STRIDE * 4)

__global__ __launch_bounds__(256, 2)
void s1_kernel(const float* __restrict__ X, const float* __restrict__ Proto,
               const float* __restrict__ Feat)
{
    extern __shared__ float sm1[];
    const int tid = threadIdx.x;
    const int wid = tid >> 5, lid = tid & 31;
    const int g = lid >> 2, tg = lid & 3;
    const int wm = wid >> 2, wn = wid & 3;
    const int rb = blockIdx.y;
    const bool isX = rb < (BDIM / 128);
    const int row0 = (isX ? rb : rb - BDIM / 128) * 128;
    const int col0 = blockIdx.x * 128;

    const float* In = isX ? X : Proto;
    float* outSq  = isX ? g_a : g_c;
    float* outInv = isX ? g_r : g_q;

    const float* gA = In   + (size_t)row0 * IDIM;
    const float* gB = Feat + (size_t)col0 * IDIM;

    float acc[4][4][4];
#pragma unroll
    for (int mi = 0; mi < 4; mi++)
#pragma unroll
        for (int ni = 0; ni < 4; ni++)
#pragma unroll
            for (int j = 0; j < 4; j++) acc[mi][ni][j] = 0.f;

    const int NIT = IDIM / 16;   // 64

#pragma unroll
    for (int s = 0; s < STAGES1 - 1; s++) {
        float* As = sm1 + s * S1_STRIDE;
        float* Bs = As + 128 * PAD;
        const int k0 = s * 16;
#pragma unroll
        for (int i = 0; i < 2; i++) {
            int idx = tid + i * 256;
            int row = idx >> 2, ch = idx & 3;
            CP16(s2u(As + row * PAD + ch * 4), gA + (size_t)row * IDIM + k0 + ch * 4);
            CP16(s2u(Bs + row * PAD + ch * 4), gB + (size_t)row * IDIM + k0 + ch * 4);
        }
        CPCOMMIT();
    }

    for (int it = 0; it < NIT; it++) {
        CPWAIT(STAGES1 - 2);
        __syncthreads();                 // single barrier per iteration

        const int nxt = it + STAGES1 - 1;
        if (nxt < NIT) {
            float* As = sm1 + (nxt % STAGES1) * S1_STRIDE;
            float* Bs = As + 128 * PAD;
            const int k0 = nxt * 16;
#pragma unroll
            for (int i = 0; i < 2; i++) {
                int idx = tid + i * 256;
                int row = idx >> 2, ch = idx & 3;
                CP16(s2u(As + row * PAD + ch * 4), gA + (size_t)row * IDIM + k0 + ch * 4);
                CP16(s2u(Bs + row * PAD + ch * 4), gB + (size_t)row * IDIM + k0 + ch * 4);
            }
        }
        CPCOMMIT();

        const float* As = sm1 + (it % STAGES1) * S1_STRIDE;
        const float* Bs = As + 128 * PAD;
#pragma unroll
        for (int ks = 0; ks < 2; ks++) {
            const int kk = ks * 8;
            uint32_t af[4][4], bf[4][2];
#pragma unroll
            for (int mi = 0; mi < 4; mi++) {
                const int r = wm * 64 + mi * 16 + g;
                af[mi][0] = f2tf(As[r * PAD + kk + tg]);
                af[mi][1] = f2tf(As[(r + 8) * PAD + kk + tg]);
                af[mi][2] = f2tf(As[r * PAD + kk + tg + 4]);
                af[mi][3] = f2tf(As[(r + 8) * PAD + kk + tg + 4]);
            }
#pragma unroll
            for (int ni = 0; ni < 4; ni++) {
                const int c = wn * 32 + ni * 8 + g;
                bf[ni][0] = f2tf(Bs[c * PAD + kk + tg]);
                bf[ni][1] = f2tf(Bs[c * PAD + kk + tg + 4]);
            }
#pragma unroll
            for (int mi = 0; mi < 4; mi++)
#pragma unroll
                for (int ni = 0; ni < 4; ni++)
                    mma8(acc[mi][ni], af[mi], bf[ni]);
        }
    }

#pragma unroll
    for (int mi = 0; mi < 4; mi++)
#pragma unroll
        for (int ni = 0; ni < 4; ni++) {
            const int rr = row0 + wm * 64 + mi * 16 + g;
            const int cc = col0 + wn * 32 + ni * 8 + tg * 2;
#pragma unroll
            for (int h = 0; h < 2; h++) {
                const float y0 = acc[mi][ni][h * 2 + 0];
                const float y1 = acc[mi][ni][h * 2 + 1];
                const float p0 = fmaxf(y0, 0.f), p1 = fmaxf(y1, 0.f);
                float2 sv = { tfr(y0 * p0), tfr(y1 * p1) };
                float2 iv = { tfr(1.f - p0), tfr(1.f - p1) };
                const size_t off = (size_t)(rr + h * 8) * FDIM + cc;
                *(float2*)&outSq[off]  = sv;
                *(float2*)&outInv[off] = iv;
            }
        }
}

// =================================================================
// Stage 2: D1 = a@c^T, D2 = a@q^T, D3 = r@c^T  over F=2048
//          out = theta*D1 - alpha*D2 - beta*D3
// CTA tile 128x64x16, 8 warps (4x2), warp tile 32x32, 3 accumulators
// =================================================================
#define S2_STRIDE (2 * 128 * PAD + 2 * 64 * PAD)
#define S2_SMEM   (STAGES2 * S2_STRIDE * 4)

__global__ __launch_bounds__(256)
void s2_kernel(const float* __restrict__ alpha, const float* __restrict__ beta,
               const float* __restrict__ theta, float* __restrict__ Out)
{
    extern __shared__ float sm2[];
    const int tid = threadIdx.x;
    const int wid = tid >> 5, lid = tid & 31;
    const int g = lid >> 2, tg = lid & 3;
    const int wm = wid >> 1, wn = wid & 1;
    const int row0 = blockIdx.y * 128, col0 = blockIdx.x * 64;

    const float* gA = g_a + (size_t)row0 * FDIM;
    const float* gR = g_r + (size_t)row0 * FDIM;
    const float* gC = g_c + (size_t)col0 * FDIM;
    const float* gQ = g_q + (size_t)col0 * FDIM;

    float a1[2][4][4], a2[2][4][4], a3[2][4][4];
#pragma unroll
    for (int mi = 0; mi < 2; mi++)
#pragma unroll
        for (int ni = 0; ni < 4; ni++)
#pragma unroll
            for (int j = 0; j < 4; j++) { a1[mi][ni][j] = 0.f; a2[mi][ni][j] = 0.f; a3[mi][ni][j] = 0.f; }

    const int NIT = FDIM / 16;   // 128

#pragma unroll
    for (int s = 0; s < STAGES2 - 1; s++) {
        float* Sa = sm2 + s * S2_STRIDE;
        float* Sr = Sa + 128 * PAD;
        float* Sc = Sr + 128 * PAD;
        float* Sq = Sc + 64 * PAD;
        const int k0 = s * 16;
#pragma unroll
        for (int i = 0; i < 2; i++) {
            int idx = tid + i * 256;
            int row = idx >> 2, ch = idx & 3;
            CP16(s2u(Sa + row * PAD + ch * 4), gA + (size_t)row * FDIM + k0 + ch * 4);
            CP16(s2u(Sr + row * PAD + ch * 4), gR + (size_t)row * FDIM + k0 + ch * 4);
        }
        { int row = tid >> 2, ch = tid & 3;
          CP16(s2u(Sc + row * PAD + ch * 4), gC + (size_t)row * FDIM + k0 + ch * 4);
          CP16(s2u(Sq + row * PAD + ch * 4), gQ + (size_t)row * FDIM + k0 + ch * 4); }
        CPCOMMIT();
    }

    for (int it = 0; it < NIT; it++) {
        CPWAIT(STAGES2 - 2);
        __syncthreads();                 // single barrier per iteration

        const int nxt = it + STAGES2 - 1;
        if (nxt < NIT) {
            float* Sa = sm2 + (nxt % STAGES2) * S2_STRIDE;
            float* Sr = Sa + 128 * PAD;
            float* Sc = Sr + 128 * PAD;
            float* Sq = Sc + 64 * PAD;
            const int k0 = nxt * 16;
#pragma unroll
            for (int i = 0; i < 2; i++) {
                int idx = tid + i * 256;
                int row = idx >> 2, ch = idx & 3;
                CP16(s2u(Sa + row * PAD + ch * 4), gA + (size_t)row * FDIM + k0 + ch * 4);
                CP16(s2u(Sr + row * PAD + ch * 4), gR + (size_t)row * FDIM + k0 + ch * 4);
            }
            { int row = tid >> 2, ch = tid & 3;
              CP16(s2u(Sc + row * PAD + ch * 4), gC + (size_t)row * FDIM + k0 + ch * 4);
              CP16(s2u(Sq + row * PAD + ch * 4), gQ + (size_t)row * FDIM + k0 + ch * 4); }
        }
        CPCOMMIT();

        const float* Sa = sm2 + (it % STAGES2) * S2_STRIDE;
        const float* Sr = Sa + 128 * PAD;
        const float* Sc = Sr + 128 * PAD;
        const float* Sq = Sc + 64 * PAD;
#pragma unroll
        for (int ks = 0; ks < 2; ks++) {
            const int kk = ks * 8;
            uint32_t af[2][4], rf[2][4], bc[4][2], bq[4][2];
#pragma unroll
            for (int mi = 0; mi < 2; mi++) {
                const int r = wm * 32 + mi * 16 + g;
                af[mi][0] = __float_as_uint(Sa[r * PAD + kk + tg]);
                af[mi][1] = __float_as_uint(Sa[(r + 8) * PAD + kk + tg]);
                af[mi][2] = __float_as_uint(Sa[r * PAD + kk + tg + 4]);
                af[mi][3] = __float_as_uint(Sa[(r + 8) * PAD + kk + tg + 4]);
                rf[mi][0] = __float_as_uint(Sr[r * PAD + kk + tg]);
                rf[mi][1] = __float_as_uint(Sr[(r + 8) * PAD + kk + tg]);
                rf[mi][2] = __float_as_uint(Sr[r * PAD + kk + tg + 4]);
                rf[mi][3] = __float_as_uint(Sr[(r + 8) * PAD + kk + tg + 4]);
            }
#pragma unroll
            for (int ni = 0; ni < 4; ni++) {
                const int c = wn * 32 + ni * 8 + g;
                bc[ni][0] = __float_as_uint(Sc[c * PAD + kk + tg]);
                bc[ni][1] = __float_as_uint(Sc[c * PAD + kk + tg + 4]);
                bq[ni][0] = __float_as_uint(Sq[c * PAD + kk + tg]);
                bq[ni][1] = __float_as_uint(Sq[c * PAD + kk + tg + 4]);
            }
#pragma unroll
            for (int mi = 0; mi < 2; mi++)
#pragma unroll
                for (int ni = 0; ni < 4; ni++) {
                    mma8(a1[mi][ni], af[mi], bc[ni]);
                    mma8(a2[mi][ni], af[mi], bq[ni]);
                    mma8(a3[mi][ni], rf[mi], bc[ni]);
                }
        }
    }

    const float al = __ldg(alpha);
    const float be = __ldg(beta);
    const float th = __ldg(theta);

#pragma unroll
    for (int mi = 0; mi < 2; mi++)
#pragma unroll
        for (int ni = 0; ni < 4; ni++) {
            const int rr = row0 + wm * 32 + mi * 16 + g;
            const int cc = col0 + wn * 32 + ni * 8 + tg * 2;
#pragma unroll
            for (int h = 0; h < 2; h++) {
                float2 o;
                o.x = th * a1[mi][ni][h * 2 + 0] - al * a2[mi][ni][h * 2 + 0] - be * a3[mi][ni][h * 2 + 0];
                o.y = th * a1[mi][ni][h * 2 + 1] - al * a2[mi][ni][h * 2 + 1] - be * a3[mi][ni][h * 2 + 1];
                *(float2*)&Out[(size_t)(rr + h * 8) * PDIM + cc] = o;
            }
        }
}

// ---------------- launch ----------------
extern "C" void kernel_launch(void* const* d_in, const int* in_sizes, int n_in,
                              void* d_out, int out_size)
{
    const float* x     = (const float*)d_in[0];
    const float* feat  = (const float*)d_in[1];
    const float* proto = (const float*)d_in[2];
    const float* alpha = (const float*)d_in[3];
    const float* beta  = (const float*)d_in[4];
    const float* theta = (const float*)d_in[5];
    float* out = (float*)d_out;

    static bool attr_done = false;
    if (!attr_done) {
        cudaFuncSetAttribute(s1_kernel, cudaFuncAttributeMaxDynamicSharedMemorySize, S1_SMEM);
        cudaFuncSetAttribute(s2_kernel, cudaFuncAttributeMaxDynamicSharedMemorySize, S2_SMEM);
        attr_done = true;
    }

    // merged stage-1: row-blocks 0..31 -> x path, 32..35 -> prototype path
    s1_kernel<<<dim3(FDIM / 128, (BDIM + PDIM) / 128), 256, S1_SMEM>>>(x, proto, feat);
    s2_kernel<<<dim3(PDIM / 64, BDIM / 128), 256, S2_SMEM>>>(alpha, beta, theta, out);
}

// round 5
// speedup vs baseline: 4.5098x; 1.4058x over previous
#include <cuda_runtime.h>
#include <cuda_bf16.h>
#include <stdint.h>

#define BDIM 4096
#define PDIM 512
#define IDIM 1024
#define FDIM 2048

#define PAD 20          // floats per 16-float smem row (stage 1)
#define STAGES1 4       // s1 pipeline depth
#define STAGES2 3       // s2 pipeline depth

// ---------------- scratch (device globals; allocation-free rule) ----------------
__device__ __align__(128) __nv_bfloat16 g_a[(size_t)BDIM * FDIM];  // bf16( xf * relu(xf) )
__device__ __align__(128) __nv_bfloat16 g_r[(size_t)BDIM * FDIM];  // bf16( 1 - relu(xf) )
__device__ __align__(128) __nv_bfloat16 g_c[(size_t)PDIM * FDIM];  // bf16( pf * relu(pf) )
__device__ __align__(128) __nv_bfloat16 g_q[(size_t)PDIM * FDIM];  // bf16( 1 - relu(pf) )

// ---------------- helpers ----------------
__device__ __forceinline__ uint32_t f2tf(float f) {
    uint32_t r; asm("cvt.rna.tf32.f32 %0, %1;" : "=r"(r) : "f"(f)); return r;
}

__device__ __forceinline__ uint32_t s2u(const void* p) {
    uint32_t a;
    asm("{ .reg .u64 t; cvta.to.shared.u64 t, %1; cvt.u32.u64 %0, t; }" : "=r"(a) : "l"(p));
    return a;
}

#define CP16(dst, src) \
    asm volatile("cp.async.cg.shared.global [%0], [%1], 16;" :: "r"(dst), "l"(src))
#define CPCOMMIT() asm volatile("cp.async.commit_group;")
#define CPWAIT(n)  asm volatile("cp.async.wait_group %0;" :: "n"(n))

__device__ __forceinline__ void mma8(float c[4], const uint32_t a[4], const uint32_t b[2]) {
    asm volatile(
        "mma.sync.aligned.m16n8k8.row.col.f32.tf32.tf32.f32 "
        "{%0,%1,%2,%3}, {%4,%5,%6,%7}, {%8,%9}, {%0,%1,%2,%3};"
        : "+f"(c[0]), "+f"(c[1]), "+f"(c[2]), "+f"(c[3])
        : "r"(a[0]), "r"(a[1]), "r"(a[2]), "r"(a[3]), "r"(b[0]), "r"(b[1]));
}

__device__ __forceinline__ void mma16(float c[4], const uint32_t a[4], const uint32_t b[2]) {
    asm volatile(
        "mma.sync.aligned.m16n8k16.row.col.f32.bf16.bf16.f32 "
        "{%0,%1,%2,%3}, {%4,%5,%6,%7}, {%8,%9}, {%0,%1,%2,%3};"
        : "+f"(c[0]), "+f"(c[1]), "+f"(c[2]), "+f"(c[3])
        : "r"(a[0]), "r"(a[1]), "r"(a[2]), "r"(a[3]), "r"(b[0]), "r"(b[1]));
}

// =================================================================
// Stage 1 (merged, tf32): Y = In @ Feat^T for BOTH x (row-blocks 0..31)
// and prototypes (row-blocks 32..35).  cvt.rna.tf32 on fragment load.
//   outSq = bf16( y * relu(y) ), outInv = bf16( 1 - relu(y) )
// CTA tile 128x128x16, 8 warps (2x4), warp tile 64x32
// =================================================================
#define S1_STRIDE (2 * 128 * PAD)
#define S1_SMEM   (STAGES1 * S1_STRIDE * 4)

__global__ __launch_bounds__(256, 2)
void s1_kernel(const float* __restrict__ X, const float* __restrict__ Proto,
               const float* __restrict__ Feat)
{
    extern __shared__ float sm1[];
    const int tid = threadIdx.x;
    const int wid = tid >> 5, lid = tid & 31;
    const int g = lid >> 2, tg = lid & 3;
    const int wm = wid >> 2, wn = wid & 3;
    const int rb = blockIdx.y;
    const bool isX = rb < (BDIM / 128);
    const int row0 = (isX ? rb : rb - BDIM / 128) * 128;
    const int col0 = blockIdx.x * 128;

    const float* In = isX ? X : Proto;
    __nv_bfloat16* outSq  = isX ? g_a : g_c;
    __nv_bfloat16* outInv = isX ? g_r : g_q;

    const float* gA = In   + (size_t)row0 * IDIM;
    const float* gB = Feat + (size_t)col0 * IDIM;

    float acc[4][4][4];
#pragma unroll
    for (int mi = 0; mi < 4; mi++)
#pragma unroll
        for (int ni = 0; ni < 4; ni++)
#pragma unroll
            for (int j = 0; j < 4; j++) acc[mi][ni][j] = 0.f;

    const int NIT = IDIM / 16;   // 64

#pragma unroll
    for (int s = 0; s < STAGES1 - 1; s++) {
        float* As = sm1 + s * S1_STRIDE;
        float* Bs = As + 128 * PAD;
        const int k0 = s * 16;
#pragma unroll
        for (int i = 0; i < 2; i++) {
            int idx = tid + i * 256;
            int row = idx >> 2, ch = idx & 3;
            CP16(s2u(As + row * PAD + ch * 4), gA + (size_t)row * IDIM + k0 + ch * 4);
            CP16(s2u(Bs + row * PAD + ch * 4), gB + (size_t)row * IDIM + k0 + ch * 4);
        }
        CPCOMMIT();
    }

    for (int it = 0; it < NIT; it++) {
        CPWAIT(STAGES1 - 2);
        __syncthreads();

        const int nxt = it + STAGES1 - 1;
        if (nxt < NIT) {
            float* As = sm1 + (nxt % STAGES1) * S1_STRIDE;
            float* Bs = As + 128 * PAD;
            const int k0 = nxt * 16;
#pragma unroll
            for (int i = 0; i < 2; i++) {
                int idx = tid + i * 256;
                int row = idx >> 2, ch = idx & 3;
                CP16(s2u(As + row * PAD + ch * 4), gA + (size_t)row * IDIM + k0 + ch * 4);
                CP16(s2u(Bs + row * PAD + ch * 4), gB + (size_t)row * IDIM + k0 + ch * 4);
            }
        }
        CPCOMMIT();

        const float* As = sm1 + (it % STAGES1) * S1_STRIDE;
        const float* Bs = As + 128 * PAD;
#pragma unroll
        for (int ks = 0; ks < 2; ks++) {
            const int kk = ks * 8;
            uint32_t af[4][4], bf[4][2];
#pragma unroll
            for (int mi = 0; mi < 4; mi++) {
                const int r = wm * 64 + mi * 16 + g;
                af[mi][0] = f2tf(As[r * PAD + kk + tg]);
                af[mi][1] = f2tf(As[(r + 8) * PAD + kk + tg]);
                af[mi][2] = f2tf(As[r * PAD + kk + tg + 4]);
                af[mi][3] = f2tf(As[(r + 8) * PAD + kk + tg + 4]);
            }
#pragma unroll
            for (int ni = 0; ni < 4; ni++) {
                const int c = wn * 32 + ni * 8 + g;
                bf[ni][0] = f2tf(Bs[c * PAD + kk + tg]);
                bf[ni][1] = f2tf(Bs[c * PAD + kk + tg + 4]);
            }
#pragma unroll
            for (int mi = 0; mi < 4; mi++)
#pragma unroll
                for (int ni = 0; ni < 4; ni++)
                    mma8(acc[mi][ni], af[mi], bf[ni]);
        }
    }

#pragma unroll
    for (int mi = 0; mi < 4; mi++)
#pragma unroll
        for (int ni = 0; ni < 4; ni++) {
            const int rr = row0 + wm * 64 + mi * 16 + g;
            const int cc = col0 + wn * 32 + ni * 8 + tg * 2;
#pragma unroll
            for (int h = 0; h < 2; h++) {
                const float y0 = acc[mi][ni][h * 2 + 0];
                const float y1 = acc[mi][ni][h * 2 + 1];
                const float p0 = fmaxf(y0, 0.f), p1 = fmaxf(y1, 0.f);
                __nv_bfloat162 sv = __floats2bfloat162_rn(y0 * p0, y1 * p1);
                __nv_bfloat162 iv = __floats2bfloat162_rn(1.f - p0, 1.f - p1);
                const size_t off = (size_t)(rr + h * 8) * FDIM + cc;
                *(__nv_bfloat162*)&outSq[off]  = sv;
                *(__nv_bfloat162*)&outInv[off] = iv;
            }
        }
}

// =================================================================
// Stage 2 (bf16, m16n8k16): D1 = a@c^T, D2 = a@q^T, D3 = r@c^T over F=2048
//          out = theta*D1 - alpha*D2 - beta*D3
// CTA tile 128x64, k-tile 32 bf16, 8 warps (4x2), warp tile 32x32
// =================================================================
#define SROW 40                                   // bf16 per smem row (32 + 8 pad)
#define S2_STRIDE ((2 * 128 + 2 * 64) * SROW)     // bf16 elems per stage
#define S2_SMEM   (STAGES2 * S2_STRIDE * 2)       // bytes (92160)

__global__ __launch_bounds__(256, 2)
void s2_kernel(const float* __restrict__ alpha, const float* __restrict__ beta,
               const float* __restrict__ theta, float* __restrict__ Out)
{
    extern __shared__ __nv_bfloat16 sm2[];
    const int tid = threadIdx.x;
    const int wid = tid >> 5, lid = tid & 31;
    const int g = lid >> 2, tg = lid & 3;
    const int wm = wid >> 1, wn = wid & 1;
    const int row0 = blockIdx.y * 128, col0 = blockIdx.x * 64;

    const __nv_bfloat16* gA = g_a + (size_t)row0 * FDIM;
    const __nv_bfloat16* gR = g_r + (size_t)row0 * FDIM;
    const __nv_bfloat16* gC = g_c + (size_t)col0 * FDIM;
    const __nv_bfloat16* gQ = g_q + (size_t)col0 * FDIM;

    float a1[2][4][4], a2[2][4][4], a3[2][4][4];
#pragma unroll
    for (int mi = 0; mi < 2; mi++)
#pragma unroll
        for (int ni = 0; ni < 4; ni++)
#pragma unroll
            for (int j = 0; j < 4; j++) { a1[mi][ni][j] = 0.f; a2[mi][ni][j] = 0.f; a3[mi][ni][j] = 0.f; }

    const int NIT = FDIM / 32;   // 64

#pragma unroll
    for (int s = 0; s < STAGES2 - 1; s++) {
        __nv_bfloat16* Sa = sm2 + s * S2_STRIDE;
        __nv_bfloat16* Sr = Sa + 128 * SROW;
        __nv_bfloat16* Sc = Sr + 128 * SROW;
        __nv_bfloat16* Sq = Sc + 64 * SROW;
        const int k0 = s * 32;
#pragma unroll
        for (int i = 0; i < 2; i++) {
            int idx = tid + i * 256;
            int row = idx >> 2, ch = idx & 3;
            CP16(s2u(Sa + row * SROW + ch * 8), gA + (size_t)row * FDIM + k0 + ch * 8);
            CP16(s2u(Sr + row * SROW + ch * 8), gR + (size_t)row * FDIM + k0 + ch * 8);
        }
        { int row = tid >> 2, ch = tid & 3;
          CP16(s2u(Sc + row * SROW + ch * 8), gC + (size_t)row * FDIM + k0 + ch * 8);
          CP16(s2u(Sq + row * SROW + ch * 8), gQ + (size_t)row * FDIM + k0 + ch * 8); }
        CPCOMMIT();
    }

    for (int it = 0; it < NIT; it++) {
        CPWAIT(STAGES2 - 2);
        __syncthreads();

        const int nxt = it + STAGES2 - 1;
        if (nxt < NIT) {
            __nv_bfloat16* Sa = sm2 + (nxt % STAGES2) * S2_STRIDE;
            __nv_bfloat16* Sr = Sa + 128 * SROW;
            __nv_bfloat16* Sc = Sr + 128 * SROW;
            __nv_bfloat16* Sq = Sc + 64 * SROW;
            const int k0 = nxt * 32;
#pragma unroll
            for (int i = 0; i < 2; i++) {
                int idx = tid + i * 256;
                int row = idx >> 2, ch = idx & 3;
                CP16(s2u(Sa + row * SROW + ch * 8), gA + (size_t)row * FDIM + k0 + ch * 8);
                CP16(s2u(Sr + row * SROW + ch * 8), gR + (size_t)row * FDIM + k0 + ch * 8);
            }
            { int row = tid >> 2, ch = tid & 3;
              CP16(s2u(Sc + row * SROW + ch * 8), gC + (size_t)row * FDIM + k0 + ch * 8);
              CP16(s2u(Sq + row * SROW + ch * 8), gQ + (size_t)row * FDIM + k0 + ch * 8); }
        }
        CPCOMMIT();

        const __nv_bfloat16* Sa = sm2 + (it % STAGES2) * S2_STRIDE;
        const __nv_bfloat16* Sr = Sa + 128 * SROW;
        const __nv_bfloat16* Sc = Sr + 128 * SROW;
        const __nv_bfloat16* Sq = Sc + 64 * SROW;
#pragma unroll
        for (int ks = 0; ks < 2; ks++) {
            const int kk = ks * 16;
            uint32_t af[2][4], rf[2][4], bc[4][2], bq[4][2];
#pragma unroll
            for (int mi = 0; mi < 2; mi++) {
                const int r = wm * 32 + mi * 16 + g;
                af[mi][0] = *(const uint32_t*)&Sa[r * SROW + kk + 2 * tg];
                af[mi][1] = *(const uint32_t*)&Sa[(r + 8) * SROW + kk + 2 * tg];
                af[mi][2] = *(const uint32_t*)&Sa[r * SROW + kk + 2 * tg + 8];
                af[mi][3] = *(const uint32_t*)&Sa[(r + 8) * SROW + kk + 2 * tg + 8];
                rf[mi][0] = *(const uint32_t*)&Sr[r * SROW + kk + 2 * tg];
                rf[mi][1] = *(const uint32_t*)&Sr[(r + 8) * SROW + kk + 2 * tg];
                rf[mi][2] = *(const uint32_t*)&Sr[r * SROW + kk + 2 * tg + 8];
                rf[mi][3] = *(const uint32_t*)&Sr[(r + 8) * SROW + kk + 2 * tg + 8];
            }
#pragma unroll
            for (int ni = 0; ni < 4; ni++) {
                const int c = wn * 32 + ni * 8 + g;
                bc[ni][0] = *(const uint32_t*)&Sc[c * SROW + kk + 2 * tg];
                bc[ni][1] = *(const uint32_t*)&Sc[c * SROW + kk + 2 * tg + 8];
                bq[ni][0] = *(const uint32_t*)&Sq[c * SROW + kk + 2 * tg];
                bq[ni][1] = *(const uint32_t*)&Sq[c * SROW + kk + 2 * tg + 8];
            }
#pragma unroll
            for (int mi = 0; mi < 2; mi++)
#pragma unroll
                for (int ni = 0; ni < 4; ni++) {
                    mma16(a1[mi][ni], af[mi], bc[ni]);
                    mma16(a2[mi][ni], af[mi], bq[ni]);
                    mma16(a3[mi][ni], rf[mi], bc[ni]);
                }
        }
    }

    const float al = __ldg(alpha);
    const float be = __ldg(beta);
    const float th = __ldg(theta);

#pragma unroll
    for (int mi = 0; mi < 2; mi++)
#pragma unroll
        for (int ni = 0; ni < 4; ni++) {
            const int rr = row0 + wm * 32 + mi * 16 + g;
            const int cc = col0 + wn * 32 + ni * 8 + tg * 2;
#pragma unroll
            for (int h = 0; h < 2; h++) {
                float2 o;
                o.x = th * a1[mi][ni][h * 2 + 0] - al * a2[mi][ni][h * 2 + 0] - be * a3[mi][ni][h * 2 + 0];
                o.y = th * a1[mi][ni][h * 2 + 1] - al * a2[mi][ni][h * 2 + 1] - be * a3[mi][ni][h * 2 + 1];
                *(float2*)&Out[(size_t)(rr + h * 8) * PDIM + cc] = o;
            }
        }
}

// ---------------- launch ----------------
extern "C" void kernel_launch(void* const* d_in, const int* in_sizes, int n_in,
                              void* d_out, int out_size)
{
    const float* x     = (const float*)d_in[0];
    const float* feat  = (const float*)d_in[1];
    const float* proto = (const float*)d_in[2];
    const float* alpha = (const float*)d_in[3];
    const float* beta  = (const float*)d_in[4];
    const float* theta = (const float*)d_in[5];
    float* out = (float*)d_out;

    static bool attr_done = false;
    if (!attr_done) {
        cudaFuncSetAttribute(s1_kernel, cudaFuncAttributeMaxDynamicSharedMemorySize, S1_SMEM);
        cudaFuncSetAttribute(s2_kernel, cudaFuncAttributeMaxDynamicSharedMemorySize, S2_SMEM);
        attr_done = true;
    }

    s1_kernel<<<dim3(FDIM / 128, (BDIM + PDIM) / 128), 256, S1_SMEM>>>(x, proto, feat);
    s2_kernel<<<dim3(PDIM / 64, BDIM / 128), 256, S2_SMEM>>>(alpha, beta, theta, out);
}

// round 6
// speedup vs baseline: 7.2445x; 1.6064x over previous
#include <cuda_runtime.h>
#include <cuda_fp16.h>
#include <cuda_bf16.h>
#include <stdint.h>

#define BDIM 4096
#define PDIM 512
#define IDIM 1024
#define FDIM 2048

#define SROW 40            // b16 elems per smem row: 32 data + 8 pad (80 B, 16B-aligned, conflict-free)
#define STAGES1 3
#define STAGES2 4

// ---------------- scratch (device globals; allocation-free rule) ----------------
__device__ __align__(128) __half g_xh[(size_t)BDIM * IDIM];
__device__ __align__(128) __half g_fh[(size_t)FDIM * IDIM];
__device__ __align__(128) __half g_ph[(size_t)PDIM * IDIM];
__device__ __align__(128) __nv_bfloat16 g_a[(size_t)BDIM * FDIM];  // xf*relu(xf)
__device__ __align__(128) __nv_bfloat16 g_w[(size_t)BDIM * FDIM];  // -beta*(1-relu(xf))
__device__ __align__(128) __nv_bfloat16 g_v[(size_t)PDIM * FDIM];  // theta*c - alpha*(1-relu(pf))
__device__ __align__(128) __nv_bfloat16 g_c[(size_t)PDIM * FDIM];  // pf*relu(pf)

// ---------------- helpers ----------------
__device__ __forceinline__ uint32_t s2u(const void* p) {
    uint32_t a;
    asm("{ .reg .u64 t; cvta.to.shared.u64 t, %1; cvt.u32.u64 %0, t; }" : "=r"(a) : "l"(p));
    return a;
}

#define CP16(dst, src) \
    asm volatile("cp.async.cg.shared.global [%0], [%1], 16;" :: "r"(dst), "l"(src))
#define CPCOMMIT() asm volatile("cp.async.commit_group;")
#define CPWAIT(n)  asm volatile("cp.async.wait_group %0;" :: "n"(n))

__device__ __forceinline__ void ldsm4(uint32_t& r0, uint32_t& r1, uint32_t& r2, uint32_t& r3,
                                      uint32_t addr) {
    asm volatile("ldmatrix.sync.aligned.m8n8.x4.shared.b16 {%0,%1,%2,%3}, [%4];"
                 : "=r"(r0), "=r"(r1), "=r"(r2), "=r"(r3) : "r"(addr));
}

__device__ __forceinline__ void mma_f16(float c[4], const uint32_t a[4], const uint32_t b[2]) {
    asm volatile(
        "mma.sync.aligned.m16n8k16.row.col.f32.f16.f16.f32 "
        "{%0,%1,%2,%3}, {%4,%5,%6,%7}, {%8,%9}, {%0,%1,%2,%3};"
        : "+f"(c[0]), "+f"(c[1]), "+f"(c[2]), "+f"(c[3])
        : "r"(a[0]), "r"(a[1]), "r"(a[2]), "r"(a[3]), "r"(b[0]), "r"(b[1]));
}

__device__ __forceinline__ void mma_bf16(float c[4], const uint32_t a[4], const uint32_t b[2]) {
    asm volatile(
        "mma.sync.aligned.m16n8k16.row.col.f32.bf16.bf16.f32 "
        "{%0,%1,%2,%3}, {%4,%5,%6,%7}, {%8,%9}, {%0,%1,%2,%3};"
        : "+f"(c[0]), "+f"(c[1]), "+f"(c[2]), "+f"(c[3])
        : "r"(a[0]), "r"(a[1]), "r"(a[2]), "r"(a[3]), "r"(b[0]), "r"(b[1]));
}

// ---------------- fp32 -> fp16 conversion prepass ----------------
__global__ void cvt_kernel(const float4* __restrict__ in, uint2* __restrict__ out, int n4)
{
    int i = blockIdx.x * blockDim.x + threadIdx.x;
    if (i < n4) {
        float4 v = in[i];
        __half2 h0 = __floats2half2_rn(v.x, v.y);
        __half2 h1 = __floats2half2_rn(v.z, v.w);
        uint2 o;
        o.x = *(uint32_t*)&h0;
        o.y = *(uint32_t*)&h1;
        out[i] = o;
    }
}

// =================================================================
// Stage 1 (fp16 m16n8k16): Y = In @ Feat^T, merged x/proto grids.
//   x-side  (rb<32): g_a = y*p,               g_w = -beta*(1-p)
//   p-side  (rb>=32): g_v = theta*y*p - alpha*(1-p), g_c = y*p
// CTA tile 128x128 k32, 8 warps (2x4), warp tile 64x32
// =================================================================
#define S1_STAGE_E (256 * SROW)            // b16 elems per stage
#define S1_STAGE_B (S1_STAGE_E * 2)        // 20480 bytes
#define S1_SMEM    (STAGES1 * S1_STAGE_B)  // 61440 bytes

__global__ __launch_bounds__(256, 2)
void s1_kernel(const float* __restrict__ alpha, const float* __restrict__ beta,
               const float* __restrict__ theta)
{
    extern __shared__ __half sm1[];
    const uint32_t sb = s2u(sm1);
    const int tid = threadIdx.x;
    const int wid = tid >> 5, lid = tid & 31;
    const int g = lid >> 2, tg = lid & 3;
    const int wm = wid >> 2, wn = wid & 3;              // 2 x 4 warps
    const int rb = blockIdx.y;
    const bool isX = rb < (BDIM / 128);
    const int row0 = (isX ? rb : rb - BDIM / 128) * 128;
    const int col0 = blockIdx.x * 128;

    const __half* In = isX ? g_xh : g_ph;
    __nv_bfloat16* out1 = isX ? g_a : g_v;
    __nv_bfloat16* out2 = isX ? g_w : g_c;

    // loader: 1024 cp16 per stage / 256 threads = 4 each
    const int r0 = tid >> 2, ch = tid & 3;
    const __half* srcA0 = In   + (size_t)(row0 + r0)      * IDIM + ch * 8;
    const __half* srcA1 = In   + (size_t)(row0 + r0 + 64) * IDIM + ch * 8;
    const __half* srcB0 = g_fh + (size_t)(col0 + r0)      * IDIM + ch * 8;
    const __half* srcB1 = g_fh + (size_t)(col0 + r0 + 64) * IDIM + ch * 8;
    const int dA0 = r0 * SROW + ch * 8;
    const int dA1 = (r0 + 64) * SROW + ch * 8;
    const int dB0 = (128 + r0) * SROW + ch * 8;
    const int dB1 = (192 + r0) * SROW + ch * 8;

    // ldmatrix lane offsets (b16 elems)
    const int aOff = ((lid & 7) + ((lid >> 3) & 1) * 8) * SROW + (lid >> 4) * 8;
    const int bOff = ((lid & 7) + (lid >> 4) * 8) * SROW + ((lid >> 3) & 1) * 8;

    float acc[4][4][4];
#pragma unroll
    for (int mi = 0; mi < 4; mi++)
#pragma unroll
        for (int ni = 0; ni < 4; ni++)
#pragma unroll
            for (int j = 0; j < 4; j++) acc[mi][ni][j] = 0.f;

    const int NIT = IDIM / 32;   // 32

#pragma unroll
    for (int s = 0; s < STAGES1 - 1; s++) {
        __half* st = sm1 + s * S1_STAGE_E;
        const int k0 = s * 32;
        CP16(s2u(st + dA0), srcA0 + k0);
        CP16(s2u(st + dA1), srcA1 + k0);
        CP16(s2u(st + dB0), srcB0 + k0);
        CP16(s2u(st + dB1), srcB1 + k0);
        CPCOMMIT();
    }

    for (int it = 0; it < NIT; it++) {
        CPWAIT(STAGES1 - 2);
        __syncthreads();

        const int nxt = it + STAGES1 - 1;
        if (nxt < NIT) {
            __half* st = sm1 + (nxt % STAGES1) * S1_STAGE_E;
            const int k0 = nxt * 32;
            CP16(s2u(st + dA0), srcA0 + k0);
            CP16(s2u(st + dA1), srcA1 + k0);
            CP16(s2u(st + dB0), srcB0 + k0);
            CP16(s2u(st + dB1), srcB1 + k0);
        }
        CPCOMMIT();

        const uint32_t su = sb + (it % STAGES1) * S1_STAGE_B;
#pragma unroll
        for (int ks = 0; ks < 2; ks++) {
            const int kk = ks * 16;
            uint32_t af[4][4], bf[4][2];
#pragma unroll
            for (int mi = 0; mi < 4; mi++) {
                const int m0 = wm * 64 + mi * 16;
                ldsm4(af[mi][0], af[mi][1], af[mi][2], af[mi][3],
                      su + 2 * (m0 * SROW + kk + aOff));
            }
#pragma unroll
            for (int nb = 0; nb < 2; nb++) {
                const int n0 = wn * 32 + nb * 16;
                ldsm4(bf[2 * nb][0], bf[2 * nb][1], bf[2 * nb + 1][0], bf[2 * nb + 1][1],
                      su + 2 * (128 * SROW + n0 * SROW + kk + bOff));
            }
#pragma unroll
            for (int mi = 0; mi < 4; mi++)
#pragma unroll
                for (int ni = 0; ni < 4; ni++)
                    mma_f16(acc[mi][ni], af[mi], bf[ni]);
        }
    }

    const float al = __ldg(alpha);
    const float be = __ldg(beta);
    const float th = __ldg(theta);

#pragma unroll
    for (int mi = 0; mi < 4; mi++)
#pragma unroll
        for (int ni = 0; ni < 4; ni++) {
            const int rr = row0 + wm * 64 + mi * 16 + g;
            const int cc = col0 + wn * 32 + ni * 8 + tg * 2;
#pragma unroll
            for (int h = 0; h < 2; h++) {
                const float y0 = acc[mi][ni][h * 2 + 0];
                const float y1 = acc[mi][ni][h * 2 + 1];
                const float p0 = fmaxf(y0, 0.f), p1 = fmaxf(y1, 0.f);
                const float yp0 = y0 * p0, yp1 = y1 * p1;
                const float iv0 = 1.f - p0, iv1 = 1.f - p1;
                float o1a, o1b, o2a, o2b;
                if (isX) { o1a = yp0;                  o1b = yp1;
                           o2a = -be * iv0;            o2b = -be * iv1; }
                else     { o1a = th * yp0 - al * iv0;  o1b = th * yp1 - al * iv1;
                           o2a = yp0;                  o2b = yp1; }
                const size_t off = (size_t)(rr + h * 8) * FDIM + cc;
                *(__nv_bfloat162*)&out1[off] = __floats2bfloat162_rn(o1a, o1b);
                *(__nv_bfloat162*)&out2[off] = __floats2bfloat162_rn(o2a, o2b);
            }
        }
}

// =================================================================
// Stage 2 (bf16 m16n8k16, single accumulator, two k-phases over F):
//   out = a @ v^T  +  w @ c^T      (phase 0: a,v ; phase 1: w,c)
// CTA tile 64x64 k32, 4 warps (2x2), warp tile 32x32
// =================================================================
#define S2_STAGE_E (128 * SROW)
#define S2_STAGE_B (S2_STAGE_E * 2)        // 10240 bytes
#define S2_SMEM    (STAGES2 * S2_STAGE_B)  // 40960 bytes
#define NIT2 (2 * FDIM / 32)               // 128
#define HALF2N (FDIM / 32)                 // 64

__global__ __launch_bounds__(128, 5)
void s2_kernel(float* __restrict__ Out)
{
    extern __shared__ __nv_bfloat16 sm2[];
    const uint32_t sb = s2u(sm2);
    const int tid = threadIdx.x;
    const int wid = tid >> 5, lid = tid & 31;
    const int g = lid >> 2, tg = lid & 3;
    const int wm = wid >> 1, wn = wid & 1;              // 2 x 2 warps
    const int row0 = blockIdx.y * 64;                   // batch rows
    const int col0 = blockIdx.x * 64;                   // prototype cols

    const int r0 = tid >> 2, ch = tid & 3;              // r0: 0..31
    const int dA0 = r0 * SROW + ch * 8;
    const int dA1 = (r0 + 32) * SROW + ch * 8;
    const int dB0 = (64 + r0) * SROW + ch * 8;
    const int dB1 = (96 + r0) * SROW + ch * 8;

    const int aOff = ((lid & 7) + ((lid >> 3) & 1) * 8) * SROW + (lid >> 4) * 8;
    const int bOff = ((lid & 7) + (lid >> 4) * 8) * SROW + ((lid >> 3) & 1) * 8;

    float acc[2][4][4];
#pragma unroll
    for (int mi = 0; mi < 2; mi++)
#pragma unroll
        for (int ni = 0; ni < 4; ni++)
#pragma unroll
            for (int j = 0; j < 4; j++) acc[mi][ni][j] = 0.f;

#pragma unroll
    for (int s = 0; s < STAGES2 - 1; s++) {
        __nv_bfloat16* st = sm2 + s * S2_STAGE_E;
        const __nv_bfloat16* A = (s < HALF2N) ? g_a : g_w;
        const __nv_bfloat16* B = (s < HALF2N) ? g_v : g_c;
        const int k0 = (s & (HALF2N - 1)) * 32;
        CP16(s2u(st + dA0), A + (size_t)(row0 + r0)      * FDIM + k0 + ch * 8);
        CP16(s2u(st + dA1), A + (size_t)(row0 + r0 + 32) * FDIM + k0 + ch * 8);
        CP16(s2u(st + dB0), B + (size_t)(col0 + r0)      * FDIM + k0 + ch * 8);
        CP16(s2u(st + dB1), B + (size_t)(col0 + r0 + 32) * FDIM + k0 + ch * 8);
        CPCOMMIT();
    }

    for (int it = 0; it < NIT2; it++) {
        CPWAIT(STAGES2 - 2);
        __syncthreads();

        const int nxt = it + STAGES2 - 1;
        if (nxt < NIT2) {
            __nv_bfloat16* st = sm2 + (nxt % STAGES2) * S2_STAGE_E;
            const __nv_bfloat16* A = (nxt < HALF2N) ? g_a : g_w;
            const __nv_bfloat16* B = (nxt < HALF2N) ? g_v : g_c;
            const int k0 = (nxt & (HALF2N - 1)) * 32;
            CP16(s2u(st + dA0), A + (size_t)(row0 + r0)      * FDIM + k0 + ch * 8);
            CP16(s2u(st + dA1), A + (size_t)(row0 + r0 + 32) * FDIM + k0 + ch * 8);
            CP16(s2u(st + dB0), B + (size_t)(col0 + r0)      * FDIM + k0 + ch * 8);
            CP16(s2u(st + dB1), B + (size_t)(col0 + r0 + 32) * FDIM + k0 + ch * 8);
        }
        CPCOMMIT();

        const uint32_t su = sb + (it % STAGES2) * S2_STAGE_B;
#pragma unroll
        for (int ks = 0; ks < 2; ks++) {
            const int kk = ks * 16;
            uint32_t af[2][4], bf[4][2];
#pragma unroll
            for (int mi = 0; mi < 2; mi++) {
                const int m0 = wm * 32 + mi * 16;
                ldsm4(af[mi][0], af[mi][1], af[mi][2], af[mi][3],
                      su + 2 * (m0 * SROW + kk + aOff));
            }
#pragma unroll
            for (int nb = 0; nb < 2; nb++) {
                const int n0 = wn * 32 + nb * 16;
                ldsm4(bf[2 * nb][0], bf[2 * nb][1], bf[2 * nb + 1][0], bf[2 * nb + 1][1],
                      su + 2 * (64 * SROW + n0 * SROW + kk + bOff));
            }
#pragma unroll
            for (int mi = 0; mi < 2; mi++)
#pragma unroll
                for (int ni = 0; ni < 4; ni++)
                    mma_bf16(acc[mi][ni], af[mi], bf[ni]);
        }
    }

#pragma unroll
    for (int mi = 0; mi < 2; mi++)
#pragma unroll
        for (int ni = 0; ni < 4; ni++) {
            const int rr = row0 + wm * 32 + mi * 16 + g;
            const int cc = col0 + wn * 32 + ni * 8 + tg * 2;
#pragma unroll
            for (int h = 0; h < 2; h++) {
                float2 o = { acc[mi][ni][h * 2 + 0], acc[mi][ni][h * 2 + 1] };
                *(float2*)&Out[(size_t)(rr + h * 8) * PDIM + cc] = o;
            }
        }
}

// ---------------- launch ----------------
extern "C" void kernel_launch(void* const* d_in, const int* in_sizes, int n_in,
                              void* d_out, int out_size)
{
    const float* x     = (const float*)d_in[0];
    const float* feat  = (const float*)d_in[1];
    const float* proto = (const float*)d_in[2];
    const float* alpha = (const float*)d_in[3];
    const float* beta  = (const float*)d_in[4];
    const float* theta = (const float*)d_in[5];
    float* out = (float*)d_out;

    __half *dxh, *dfh, *dph;
    cudaGetSymbolAddress((void**)&dxh, g_xh);
    cudaGetSymbolAddress((void**)&dfh, g_fh);
    cudaGetSymbolAddress((void**)&dph, g_ph);

    static bool attr_done = false;
    if (!attr_done) {
        cudaFuncSetAttribute(s1_kernel, cudaFuncAttributeMaxDynamicSharedMemorySize, S1_SMEM);
        cudaFuncSetAttribute(s2_kernel, cudaFuncAttributeMaxDynamicSharedMemorySize, S2_SMEM);
        attr_done = true;
    }

    cvt_kernel<<<BDIM * IDIM / 4 / 256, 256>>>((const float4*)x,     (uint2*)dxh, BDIM * IDIM / 4);
    cvt_kernel<<<FDIM * IDIM / 4 / 256, 256>>>((const float4*)feat,  (uint2*)dfh, FDIM * IDIM / 4);
    cvt_kernel<<<PDIM * IDIM / 4 / 256, 256>>>((const float4*)proto, (uint2*)dph, PDIM * IDIM / 4);

    s1_kernel<<<dim3(FDIM / 128, (BDIM + PDIM) / 128), 256, S1_SMEM>>>(alpha, beta, theta);
    s2_kernel<<<dim3(PDIM / 64, BDIM / 64), 128, S2_SMEM>>>(out);
}

// round 7
// speedup vs baseline: 7.5081x; 1.0364x over previous
#include <cuda_runtime.h>
#include <cuda_fp16.h>
#include <cuda_bf16.h>
#include <stdint.h>

#define BDIM 4096
#define PDIM 512
#define IDIM 1024
#define FDIM 2048

// ---------------- scratch (device globals; allocation-free rule) ----------------
__device__ __align__(128) __half g_xh[(size_t)BDIM * IDIM];
__device__ __align__(128) __half g_fh[(size_t)FDIM * IDIM];
__device__ __align__(128) __half g_ph[(size_t)PDIM * IDIM];
__device__ __align__(128) __nv_bfloat16 g_a[(size_t)BDIM * FDIM];  // xf*relu(xf)
__device__ __align__(128) __nv_bfloat16 g_w[(size_t)BDIM * FDIM];  // -beta*(1-relu(xf))
__device__ __align__(128) __nv_bfloat16 g_v[(size_t)PDIM * FDIM];  // theta*c - alpha*(1-relu(pf))
__device__ __align__(128) __nv_bfloat16 g_c[(size_t)PDIM * FDIM];  // pf*relu(pf)

// ---------------- helpers ----------------
__device__ __forceinline__ uint32_t s2u(const void* p) {
    uint32_t a;
    asm("{ .reg .u64 t; cvta.to.shared.u64 t, %1; cvt.u32.u64 %0, t; }" : "=r"(a) : "l"(p));
    return a;
}

#define CP16(dst, src) \
    asm volatile("cp.async.cg.shared.global [%0], [%1], 16;" :: "r"(dst), "l"(src))
#define CPCOMMIT() asm volatile("cp.async.commit_group;")
#define CPWAIT(n)  asm volatile("cp.async.wait_group %0;" :: "n"(n))

__device__ __forceinline__ void ldsm4(uint32_t& r0, uint32_t& r1, uint32_t& r2, uint32_t& r3,
                                      uint32_t addr) {
    asm volatile("ldmatrix.sync.aligned.m8n8.x4.shared.b16 {%0,%1,%2,%3}, [%4];"
                 : "=r"(r0), "=r"(r1), "=r"(r2), "=r"(r3) : "r"(addr));
}

__device__ __forceinline__ void mma_f16(float c[4], const uint32_t a[4], const uint32_t b[2]) {
    asm volatile(
        "mma.sync.aligned.m16n8k16.row.col.f32.f16.f16.f32 "
        "{%0,%1,%2,%3}, {%4,%5,%6,%7}, {%8,%9}, {%0,%1,%2,%3};"
        : "+f"(c[0]), "+f"(c[1]), "+f"(c[2]), "+f"(c[3])
        : "r"(a[0]), "r"(a[1]), "r"(a[2]), "r"(a[3]), "r"(b[0]), "r"(b[1]));
}

__device__ __forceinline__ void mma_bf16(float c[4], const uint32_t a[4], const uint32_t b[2]) {
    asm volatile(
        "mma.sync.aligned.m16n8k16.row.col.f32.bf16.bf16.f32 "
        "{%0,%1,%2,%3}, {%4,%5,%6,%7}, {%8,%9}, {%0,%1,%2,%3};"
        : "+f"(c[0]), "+f"(c[1]), "+f"(c[2]), "+f"(c[3])
        : "r"(a[0]), "r"(a[1]), "r"(a[2]), "r"(a[3]), "r"(b[0]), "r"(b[1]));
}

// ---------------- merged fp32 -> fp16 conversion (one launch) ----------------
__global__ void cvt_all(const float4* __restrict__ x, const float4* __restrict__ f,
                        const float4* __restrict__ p)
{
    const int nx = BDIM * IDIM / 4, nf = FDIM * IDIM / 4, np = PDIM * IDIM / 4;
    int i = blockIdx.x * blockDim.x + threadIdx.x;
    const float4* src; uint2* dst; int j;
    if (i < nx)                { src = x; dst = (uint2*)g_xh; j = i; }
    else if (i < nx + nf)      { src = f; dst = (uint2*)g_fh; j = i - nx; }
    else if (i < nx + nf + np) { src = p; dst = (uint2*)g_ph; j = i - nx - nf; }
    else return;
    float4 v = src[j];
    __half2 h0 = __floats2half2_rn(v.x, v.y);
    __half2 h1 = __floats2half2_rn(v.z, v.w);
    uint2 o; o.x = *(uint32_t*)&h0; o.y = *(uint32_t*)&h1;
    dst[j] = o;
}

// =================================================================
// Stage 1 (fp16 m16n8k16): Y = In @ Feat^T, merged x/proto grids.
//   x-side  (rb<32): g_a = y*p,                    g_w = -beta*(1-p)
//   p-side (rb>=32): g_v = theta*y*p - alpha*(1-p), g_c = y*p
// CTA 128x128, k-tile 64, 3-stage cp.async, 8 warps (2x4), warp 64x32,
// fragment double-buffering across the 4 k16 slices.
// =================================================================
#define SROW1 72                            // 64 data + 8 pad halfs (144 B row)
#define S1_STAGE_E (256 * SROW1)            // halfs per stage
#define S1_STAGE_B (S1_STAGE_E * 2)         // 36864 bytes
#define STAGES1 3
#define S1_SMEM (STAGES1 * S1_STAGE_B)      // 110592 bytes

__global__ __launch_bounds__(256, 2)
void s1_kernel(const float* __restrict__ alpha, const float* __restrict__ beta,
               const float* __restrict__ theta)
{
    extern __shared__ __half sm1[];
    const uint32_t sb = s2u(sm1);
    const int tid = threadIdx.x;
    const int wid = tid >> 5, lid = tid & 31;
    const int g = lid >> 2, tg = lid & 3;
    const int wm = wid >> 2, wn = wid & 3;              // 2 x 4 warps
    const int rb = blockIdx.y;
    const bool isX = rb < (BDIM / 128);
    const int row0 = (isX ? rb : rb - BDIM / 128) * 128;
    const int col0 = blockIdx.x * 128;

    const __half* In = isX ? g_xh : g_ph;
    __nv_bfloat16* out1 = isX ? g_a : g_v;
    __nv_bfloat16* out2 = isX ? g_w : g_c;

    // loader: 2048 cp16 per stage / 256 threads = 8 each (4 A rows + 4 B rows)
    const int r0 = tid >> 3, ch = tid & 7;              // r0: 0..31, ch: 0..7
    const __half* srcA = In   + (size_t)(row0 + r0) * IDIM + ch * 8;
    const __half* srcB = g_fh + (size_t)(col0 + r0) * IDIM + ch * 8;
    const int dBase = r0 * SROW1 + ch * 8;

    // ldmatrix lane offsets (in b16 elems)
    const int aOff = ((lid & 7) + ((lid >> 3) & 1) * 8) * SROW1 + (lid >> 4) * 8;
    const int bOff = ((lid & 7) + (lid >> 4) * 8) * SROW1 + ((lid >> 3) & 1) * 8;

    float acc[4][4][4];
#pragma unroll
    for (int mi = 0; mi < 4; mi++)
#pragma unroll
        for (int ni = 0; ni < 4; ni++)
#pragma unroll
            for (int j = 0; j < 4; j++) acc[mi][ni][j] = 0.f;

    const int NIT = IDIM / 64;   // 16

#pragma unroll
    for (int s = 0; s < STAGES1 - 1; s++) {
        __half* st = sm1 + s * S1_STAGE_E;
        const int k0 = s * 64;
#pragma unroll
        for (int i = 0; i < 4; i++) {
            CP16(s2u(st + dBase + i * 32 * SROW1), srcA + (size_t)(i * 32) * IDIM + k0);
            CP16(s2u(st + dBase + (128 + i * 32) * SROW1), srcB + (size_t)(i * 32) * IDIM + k0);
        }
        CPCOMMIT();
    }

    for (int it = 0; it < NIT; it++) {
        CPWAIT(STAGES1 - 2);
        __syncthreads();

        const int nxt = it + STAGES1 - 1;
        if (nxt < NIT) {
            __half* st = sm1 + (nxt % STAGES1) * S1_STAGE_E;
            const int k0 = nxt * 64;
#pragma unroll
            for (int i = 0; i < 4; i++) {
                CP16(s2u(st + dBase + i * 32 * SROW1), srcA + (size_t)(i * 32) * IDIM + k0);
                CP16(s2u(st + dBase + (128 + i * 32) * SROW1), srcB + (size_t)(i * 32) * IDIM + k0);
            }
        }
        CPCOMMIT();

        const uint32_t su = sb + (it % STAGES1) * S1_STAGE_B;
        const uint32_t aBase = su + 2 * (wm * 64 * SROW1 + aOff);
        const uint32_t bBase = su + 2 * ((128 + wn * 32) * SROW1 + bOff);

        uint32_t af[2][4][4], bf[2][4][2];
        // preload k-slice 0
#pragma unroll
        for (int mi = 0; mi < 4; mi++)
            ldsm4(af[0][mi][0], af[0][mi][1], af[0][mi][2], af[0][mi][3],
                  aBase + 2 * (mi * 16 * SROW1));
#pragma unroll
        for (int nb = 0; nb < 2; nb++)
            ldsm4(bf[0][2 * nb][0], bf[0][2 * nb][1], bf[0][2 * nb + 1][0], bf[0][2 * nb + 1][1],
                  bBase + 2 * (nb * 16 * SROW1));

#pragma unroll
        for (int ks = 0; ks < 4; ks++) {
            const int cur = ks & 1, nx2 = cur ^ 1;
            if (ks < 3) {
                const int kk = (ks + 1) * 16;
#pragma unroll
                for (int mi = 0; mi < 4; mi++)
                    ldsm4(af[nx2][mi][0], af[nx2][mi][1], af[nx2][mi][2], af[nx2][mi][3],
                          aBase + 2 * (mi * 16 * SROW1 + kk));
#pragma unroll
                for (int nb = 0; nb < 2; nb++)
                    ldsm4(bf[nx2][2 * nb][0], bf[nx2][2 * nb][1],
                          bf[nx2][2 * nb + 1][0], bf[nx2][2 * nb + 1][1],
                          bBase + 2 * (nb * 16 * SROW1 + kk));
            }
#pragma unroll
            for (int mi = 0; mi < 4; mi++)
#pragma unroll
                for (int ni = 0; ni < 4; ni++)
                    mma_f16(acc[mi][ni], af[cur][mi], bf[cur][ni]);
        }
    }

    const float al = __ldg(alpha);
    const float be = __ldg(beta);
    const float th = __ldg(theta);

#pragma unroll
    for (int mi = 0; mi < 4; mi++)
#pragma unroll
        for (int ni = 0; ni < 4; ni++) {
            const int rr = row0 + wm * 64 + mi * 16 + g;
            const int cc = col0 + wn * 32 + ni * 8 + tg * 2;
#pragma unroll
            for (int h = 0; h < 2; h++) {
                const float y0 = acc[mi][ni][h * 2 + 0];
                const float y1 = acc[mi][ni][h * 2 + 1];
                const float p0 = fmaxf(y0, 0.f), p1 = fmaxf(y1, 0.f);
                const float yp0 = y0 * p0, yp1 = y1 * p1;
                const float iv0 = 1.f - p0, iv1 = 1.f - p1;
                float o1a, o1b, o2a, o2b;
                if (isX) { o1a = yp0;                  o1b = yp1;
                           o2a = -be * iv0;            o2b = -be * iv1; }
                else     { o1a = th * yp0 - al * iv0;  o1b = th * yp1 - al * iv1;
                           o2a = yp0;                  o2b = yp1; }
                const size_t off = (size_t)(rr + h * 8) * FDIM + cc;
                *(__nv_bfloat162*)&out1[off] = __floats2bfloat162_rn(o1a, o1b);
                *(__nv_bfloat162*)&out2[off] = __floats2bfloat162_rn(o2a, o2b);
            }
        }
}

// =================================================================
// Stage 2 (bf16 m16n8k16, single accumulator, two k-phases over F):
//   out = a @ v^T  +  w @ c^T      (phase 0: a,v ; phase 1: w,c)
// CTA tile 64x64 k32, 4 warps (2x2), warp tile 32x32
// =================================================================
#define SROW 40
#define STAGES2 4
#define S2_STAGE_E (128 * SROW)
#define S2_STAGE_B (S2_STAGE_E * 2)        // 10240 bytes
#define S2_SMEM    (STAGES2 * S2_STAGE_B)  // 40960 bytes
#define NIT2 (2 * FDIM / 32)               // 128
#define HALF2N (FDIM / 32)                 // 64

__global__ __launch_bounds__(128, 5)
void s2_kernel(float* __restrict__ Out)
{
    extern __shared__ __nv_bfloat16 sm2[];
    const uint32_t sb = s2u(sm2);
    const int tid = threadIdx.x;
    const int wid = tid >> 5, lid = tid & 31;
    const int g = lid >> 2, tg = lid & 3;
    const int wm = wid >> 1, wn = wid & 1;              // 2 x 2 warps
    const int row0 = blockIdx.y * 64;
    const int col0 = blockIdx.x * 64;

    const int r0 = tid >> 2, ch = tid & 3;              // r0: 0..31
    const int dA0 = r0 * SROW + ch * 8;
    const int dA1 = (r0 + 32) * SROW + ch * 8;
    const int dB0 = (64 + r0) * SROW + ch * 8;
    const int dB1 = (96 + r0) * SROW + ch * 8;

    const int aOff = ((lid & 7) + ((lid >> 3) & 1) * 8) * SROW + (lid >> 4) * 8;
    const int bOff = ((lid & 7) + (lid >> 4) * 8) * SROW + ((lid >> 3) & 1) * 8;

    float acc[2][4][4];
#pragma unroll
    for (int mi = 0; mi < 2; mi++)
#pragma unroll
        for (int ni = 0; ni < 4; ni++)
#pragma unroll
            for (int j = 0; j < 4; j++) acc[mi][ni][j] = 0.f;

#pragma unroll
    for (int s = 0; s < STAGES2 - 1; s++) {
        __nv_bfloat16* st = sm2 + s * S2_STAGE_E;
        const __nv_bfloat16* A = (s < HALF2N) ? g_a : g_w;
        const __nv_bfloat16* B = (s < HALF2N) ? g_v : g_c;
        const int k0 = (s & (HALF2N - 1)) * 32;
        CP16(s2u(st + dA0), A + (size_t)(row0 + r0)      * FDIM + k0 + ch * 8);
        CP16(s2u(st + dA1), A + (size_t)(row0 + r0 + 32) * FDIM + k0 + ch * 8);
        CP16(s2u(st + dB0), B + (size_t)(col0 + r0)      * FDIM + k0 + ch * 8);
        CP16(s2u(st + dB1), B + (size_t)(col0 + r0 + 32) * FDIM + k0 + ch * 8);
        CPCOMMIT();
    }

    for (int it = 0; it < NIT2; it++) {
        CPWAIT(STAGES2 - 2);
        __syncthreads();

        const int nxt = it + STAGES2 - 1;
        if (nxt < NIT2) {
            __nv_bfloat16* st = sm2 + (nxt % STAGES2) * S2_STAGE_E;
            const __nv_bfloat16* A = (nxt < HALF2N) ? g_a : g_w;
            const __nv_bfloat16* B = (nxt < HALF2N) ? g_v : g_c;
            const int k0 = (nxt & (HALF2N - 1)) * 32;
            CP16(s2u(st + dA0), A + (size_t)(row0 + r0)      * FDIM + k0 + ch * 8);
            CP16(s2u(st + dA1), A + (size_t)(row0 + r0 + 32) * FDIM + k0 + ch * 8);
            CP16(s2u(st + dB0), B + (size_t)(col0 + r0)      * FDIM + k0 + ch * 8);
            CP16(s2u(st + dB1), B + (size_t)(col0 + r0 + 32) * FDIM + k0 + ch * 8);
        }
        CPCOMMIT();

        const uint32_t su = sb + (it % STAGES2) * S2_STAGE_B;
#pragma unroll
        for (int ks = 0; ks < 2; ks++) {
            const int kk = ks * 16;
            uint32_t af[2][4], bf[4][2];
#pragma unroll
            for (int mi = 0; mi < 2; mi++) {
                const int m0 = wm * 32 + mi * 16;
                ldsm4(af[mi][0], af[mi][1], af[mi][2], af[mi][3],
                      su + 2 * (m0 * SROW + kk + aOff));
            }
#pragma unroll
            for (int nb = 0; nb < 2; nb++) {
                const int n0 = wn * 32 + nb * 16;
                ldsm4(bf[2 * nb][0], bf[2 * nb][1], bf[2 * nb + 1][0], bf[2 * nb + 1][1],
                      su + 2 * (64 * SROW + n0 * SROW + kk + bOff));
            }
#pragma unroll
            for (int mi = 0; mi < 2; mi++)
#pragma unroll
                for (int ni = 0; ni < 4; ni++)
                    mma_bf16(acc[mi][ni], af[mi], bf[ni]);
        }
    }

#pragma unroll
    for (int mi = 0; mi < 2; mi++)
#pragma unroll
        for (int ni = 0; ni < 4; ni++) {
            const int rr = row0 + wm * 32 + mi * 16 + g;
            const int cc = col0 + wn * 32 + ni * 8 + tg * 2;
#pragma unroll
            for (int h = 0; h < 2; h++) {
                float2 o = { acc[mi][ni][h * 2 + 0], acc[mi][ni][h * 2 + 1] };
                *(float2*)&Out[(size_t)(rr + h * 8) * PDIM + cc] = o;
            }
        }
}

// ---------------- launch ----------------
extern "C" void kernel_launch(void* const* d_in, const int* in_sizes, int n_in,
                              void* d_out, int out_size)
{
    const float* x     = (const float*)d_in[0];
    const float* feat  = (const float*)d_in[1];
    const float* proto = (const float*)d_in[2];
    const float* alpha = (const float*)d_in[3];
    const float* beta  = (const float*)d_in[4];
    const float* theta = (const float*)d_in[5];
    float* out = (float*)d_out;

    static bool attr_done = false;
    if (!attr_done) {
        cudaFuncSetAttribute(s1_kernel, cudaFuncAttributeMaxDynamicSharedMemorySize, S1_SMEM);
        cudaFuncSetAttribute(s2_kernel, cudaFuncAttributeMaxDynamicSharedMemorySize, S2_SMEM);
        attr_done = true;
    }

    const int ntot = (BDIM + FDIM + PDIM) * IDIM / 4;
    cvt_all<<<(ntot + 255) / 256, 256>>>((const float4*)x, (const float4*)feat,
                                         (const float4*)proto);
    s1_kernel<<<dim3(FDIM / 128, (BDIM + PDIM) / 128), 256, S1_SMEM>>>(alpha, beta, theta);
    s2_kernel<<<dim3(PDIM / 64, BDIM / 64), 128, S2_SMEM>>>(out);
}

// round 8
// speedup vs baseline: 8.4124x; 1.1204x over previous
#include <cuda_runtime.h>
#include <cuda_fp16.h>
#include <cuda_bf16.h>
#include <stdint.h>

#define BDIM 4096
#define PDIM 512
#define IDIM 1024
#define FDIM 2048

// ---------------- scratch (device globals; allocation-free rule) ----------------
__device__ __align__(128) __half g_xh[(size_t)BDIM * IDIM];
__device__ __align__(128) __half g_fh[(size_t)FDIM * IDIM];
__device__ __align__(128) __half g_ph[(size_t)PDIM * IDIM];
__device__ __align__(128) __nv_bfloat16 g_a[(size_t)BDIM * FDIM];  // xf*relu(xf)
__device__ __align__(128) __nv_bfloat16 g_w[(size_t)BDIM * FDIM];  // -beta*(1-relu(xf))
__device__ __align__(128) __nv_bfloat16 g_v[(size_t)PDIM * FDIM];  // theta*c - alpha*(1-relu(pf))
__device__ __align__(128) __nv_bfloat16 g_c[(size_t)PDIM * FDIM];  // pf*relu(pf)

// ---------------- helpers ----------------
__device__ __forceinline__ uint32_t s2u(const void* p) {
    uint32_t a;
    asm("{ .reg .u64 t; cvta.to.shared.u64 t, %1; cvt.u32.u64 %0, t; }" : "=r"(a) : "l"(p));
    return a;
}

#define CP16(dst, src) \
    asm volatile("cp.async.cg.shared.global [%0], [%1], 16;" :: "r"(dst), "l"(src))
#define CPCOMMIT() asm volatile("cp.async.commit_group;")
#define CPWAIT(n)  asm volatile("cp.async.wait_group %0;" :: "n"(n))

__device__ __forceinline__ void ldsm4(uint32_t& r0, uint32_t& r1, uint32_t& r2, uint32_t& r3,
                                      uint32_t addr) {
    asm volatile("ldmatrix.sync.aligned.m8n8.x4.shared.b16 {%0,%1,%2,%3}, [%4];"
                 : "=r"(r0), "=r"(r1), "=r"(r2), "=r"(r3) : "r"(addr));
}

__device__ __forceinline__ void mma_f16(float c[4], const uint32_t a[4], const uint32_t b[2]) {
    asm volatile(
        "mma.sync.aligned.m16n8k16.row.col.f32.f16.f16.f32 "
        "{%0,%1,%2,%3}, {%4,%5,%6,%7}, {%8,%9}, {%0,%1,%2,%3};"
        : "+f"(c[0]), "+f"(c[1]), "+f"(c[2]), "+f"(c[3])
        : "r"(a[0]), "r"(a[1]), "r"(a[2]), "r"(a[3]), "r"(b[0]), "r"(b[1]));
}

__device__ __forceinline__ void mma_bf16(float c[4], const uint32_t a[4], const uint32_t b[2]) {
    asm volatile(
        "mma.sync.aligned.m16n8k16.row.col.f32.bf16.bf16.f32 "
        "{%0,%1,%2,%3}, {%4,%5,%6,%7}, {%8,%9}, {%0,%1,%2,%3};"
        : "+f"(c[0]), "+f"(c[1]), "+f"(c[2]), "+f"(c[3])
        : "r"(a[0]), "r"(a[1]), "r"(a[2]), "r"(a[3]), "r"(b[0]), "r"(b[1]));
}

// ---------------- merged fp32 -> fp16 conversion (one launch) ----------------
__global__ void cvt_all(const float4* __restrict__ x, const float4* __restrict__ f,
                        const float4* __restrict__ p)
{
    const int nx = BDIM * IDIM / 4, nf = FDIM * IDIM / 4, np = PDIM * IDIM / 4;
    int i = blockIdx.x * blockDim.x + threadIdx.x;
    const float4* src; uint2* dst; int j;
    if (i < nx)                { src = x; dst = (uint2*)g_xh; j = i; }
    else if (i < nx + nf)      { src = f; dst = (uint2*)g_fh; j = i - nx; }
    else if (i < nx + nf + np) { src = p; dst = (uint2*)g_ph; j = i - nx - nf; }
    else return;
    float4 v = src[j];
    __half2 h0 = __floats2half2_rn(v.x, v.y);
    __half2 h1 = __floats2half2_rn(v.z, v.w);
    uint2 o; o.x = *(uint32_t*)&h0; o.y = *(uint32_t*)&h1;
    dst[j] = o;
}

// =================================================================
// Stage 1 (fp16 m16n8k16): Y = In @ Feat^T, merged x/proto grids.
//   x-side  (rb<32): g_a = y*p,                    g_w = -beta*(1-p)
//   p-side (rb>=32): g_v = theta*y*p - alpha*(1-p), g_c = y*p
// CTA 128x128, k-tile 64, 3-stage cp.async, 8 warps (2x4), warp 64x32,
// fragment double-buffering across the 4 k16 slices.
// =================================================================
#define SROW1 72
#define S1_STAGE_E (256 * SROW1)
#define S1_STAGE_B (S1_STAGE_E * 2)
#define STAGES1 3
#define S1_SMEM (STAGES1 * S1_STAGE_B)

__global__ __launch_bounds__(256, 2)
void s1_kernel(const float* __restrict__ alpha, const float* __restrict__ beta,
               const float* __restrict__ theta)
{
    extern __shared__ __half sm1[];
    const uint32_t sb = s2u(sm1);
    const int tid = threadIdx.x;
    const int wid = tid >> 5, lid = tid & 31;
    const int g = lid >> 2, tg = lid & 3;
    const int wm = wid >> 2, wn = wid & 3;
    const int rb = blockIdx.y;
    const bool isX = rb < (BDIM / 128);
    const int row0 = (isX ? rb : rb - BDIM / 128) * 128;
    const int col0 = blockIdx.x * 128;

    const __half* In = isX ? g_xh : g_ph;
    __nv_bfloat16* out1 = isX ? g_a : g_v;
    __nv_bfloat16* out2 = isX ? g_w : g_c;

    const int r0 = tid >> 3, ch = tid & 7;
    const __half* srcA = In   + (size_t)(row0 + r0) * IDIM + ch * 8;
    const __half* srcB = g_fh + (size_t)(col0 + r0) * IDIM + ch * 8;
    const int dBase = r0 * SROW1 + ch * 8;

    const int aOff = ((lid & 7) + ((lid >> 3) & 1) * 8) * SROW1 + (lid >> 4) * 8;
    const int bOff = ((lid & 7) + (lid >> 4) * 8) * SROW1 + ((lid >> 3) & 1) * 8;

    float acc[4][4][4];
#pragma unroll
    for (int mi = 0; mi < 4; mi++)
#pragma unroll
        for (int ni = 0; ni < 4; ni++)
#pragma unroll
            for (int j = 0; j < 4; j++) acc[mi][ni][j] = 0.f;

    const int NIT = IDIM / 64;

#pragma unroll
    for (int s = 0; s < STAGES1 - 1; s++) {
        __half* st = sm1 + s * S1_STAGE_E;
        const int k0 = s * 64;
#pragma unroll
        for (int i = 0; i < 4; i++) {
            CP16(s2u(st + dBase + i * 32 * SROW1), srcA + (size_t)(i * 32) * IDIM + k0);
            CP16(s2u(st + dBase + (128 + i * 32) * SROW1), srcB + (size_t)(i * 32) * IDIM + k0);
        }
        CPCOMMIT();
    }

    for (int it = 0; it < NIT; it++) {
        CPWAIT(STAGES1 - 2);
        __syncthreads();

        const int nxt = it + STAGES1 - 1;
        if (nxt < NIT) {
            __half* st = sm1 + (nxt % STAGES1) * S1_STAGE_E;
            const int k0 = nxt * 64;
#pragma unroll
            for (int i = 0; i < 4; i++) {
                CP16(s2u(st + dBase + i * 32 * SROW1), srcA + (size_t)(i * 32) * IDIM + k0);
                CP16(s2u(st + dBase + (128 + i * 32) * SROW1), srcB + (size_t)(i * 32) * IDIM + k0);
            }
        }
        CPCOMMIT();

        const uint32_t su = sb + (it % STAGES1) * S1_STAGE_B;
        const uint32_t aBase = su + 2 * (wm * 64 * SROW1 + aOff);
        const uint32_t bBase = su + 2 * ((128 + wn * 32) * SROW1 + bOff);

        uint32_t af[2][4][4], bf[2][4][2];
#pragma unroll
        for (int mi = 0; mi < 4; mi++)
            ldsm4(af[0][mi][0], af[0][mi][1], af[0][mi][2], af[0][mi][3],
                  aBase + 2 * (mi * 16 * SROW1));
#pragma unroll
        for (int nb = 0; nb < 2; nb++)
            ldsm4(bf[0][2 * nb][0], bf[0][2 * nb][1], bf[0][2 * nb + 1][0], bf[0][2 * nb + 1][1],
                  bBase + 2 * (nb * 16 * SROW1));

#pragma unroll
        for (int ks = 0; ks < 4; ks++) {
            const int cur = ks & 1, nx2 = cur ^ 1;
            if (ks < 3) {
                const int kk = (ks + 1) * 16;
#pragma unroll
                for (int mi = 0; mi < 4; mi++)
                    ldsm4(af[nx2][mi][0], af[nx2][mi][1], af[nx2][mi][2], af[nx2][mi][3],
                          aBase + 2 * (mi * 16 * SROW1 + kk));
#pragma unroll
                for (int nb = 0; nb < 2; nb++)
                    ldsm4(bf[nx2][2 * nb][0], bf[nx2][2 * nb][1],
                          bf[nx2][2 * nb + 1][0], bf[nx2][2 * nb + 1][1],
                          bBase + 2 * (nb * 16 * SROW1 + kk));
            }
#pragma unroll
            for (int mi = 0; mi < 4; mi++)
#pragma unroll
                for (int ni = 0; ni < 4; ni++)
                    mma_f16(acc[mi][ni], af[cur][mi], bf[cur][ni]);
        }
    }

    const float al = __ldg(alpha);
    const float be = __ldg(beta);
    const float th = __ldg(theta);

#pragma unroll
    for (int mi = 0; mi < 4; mi++)
#pragma unroll
        for (int ni = 0; ni < 4; ni++) {
            const int rr = row0 + wm * 64 + mi * 16 + g;
            const int cc = col0 + wn * 32 + ni * 8 + tg * 2;
#pragma unroll
            for (int h = 0; h < 2; h++) {
                const float y0 = acc[mi][ni][h * 2 + 0];
                const float y1 = acc[mi][ni][h * 2 + 1];
                const float p0 = fmaxf(y0, 0.f), p1 = fmaxf(y1, 0.f);
                const float yp0 = y0 * p0, yp1 = y1 * p1;
                const float iv0 = 1.f - p0, iv1 = 1.f - p1;
                float o1a, o1b, o2a, o2b;
                if (isX) { o1a = yp0;                  o1b = yp1;
                           o2a = -be * iv0;            o2b = -be * iv1; }
                else     { o1a = th * yp0 - al * iv0;  o1b = th * yp1 - al * iv1;
                           o2a = yp0;                  o2b = yp1; }
                const size_t off = (size_t)(rr + h * 8) * FDIM + cc;
                *(__nv_bfloat162*)&out1[off] = __floats2bfloat162_rn(o1a, o1b);
                *(__nv_bfloat162*)&out2[off] = __floats2bfloat162_rn(o2a, o2b);
            }
        }
}

// =================================================================
// Stage 2 (bf16 m16n8k16): out = a @ v^T + w @ c^T (two k-phases over F)
// CTA 128x64, k-tile 32, 3-stage cp.async, 4 warps (2x2), warp 64x32,
// fragment double-buffering across the 2 k16 slices.
// =================================================================
#define SROW 40
#define STAGES2 3
#define S2_STAGE_E (192 * SROW)            // 128 A rows + 64 B rows
#define S2_STAGE_B (S2_STAGE_E * 2)        // 15360 bytes
#define S2_SMEM    (STAGES2 * S2_STAGE_B)  // 46080 bytes
#define NIT2 (2 * FDIM / 32)               // 128
#define HALF2N (FDIM / 32)                 // 64

__global__ __launch_bounds__(128, 4)
void s2_kernel(float* __restrict__ Out)
{
    extern __shared__ __nv_bfloat16 sm2[];
    const uint32_t sb = s2u(sm2);
    const int tid = threadIdx.x;
    const int wid = tid >> 5, lid = tid & 31;
    const int g = lid >> 2, tg = lid & 3;
    const int wm = wid >> 1, wn = wid & 1;              // 2 x 2 warps, warp 64x32
    const int row0 = blockIdx.y * 128;
    const int col0 = blockIdx.x * 64;

    // loader: 768 cp16 per stage / 128 threads = 6 each (4 A + 2 B)
    const int r0 = tid >> 2, ch = tid & 3;              // r0: 0..31, ch: 0..3
    const int dBase = r0 * SROW + ch * 8;

    const int aOff = ((lid & 7) + ((lid >> 3) & 1) * 8) * SROW + (lid >> 4) * 8;
    const int bOff = ((lid & 7) + (lid >> 4) * 8) * SROW + ((lid >> 3) & 1) * 8;

    float acc[4][4][4];
#pragma unroll
    for (int mi = 0; mi < 4; mi++)
#pragma unroll
        for (int ni = 0; ni < 4; ni++)
#pragma unroll
            for (int j = 0; j < 4; j++) acc[mi][ni][j] = 0.f;

#pragma unroll
    for (int s = 0; s < STAGES2 - 1; s++) {
        __nv_bfloat16* st = sm2 + s * S2_STAGE_E;
        const __nv_bfloat16* A = (s < HALF2N) ? g_a : g_w;
        const __nv_bfloat16* B = (s < HALF2N) ? g_v : g_c;
        const int k0 = (s & (HALF2N - 1)) * 32;
#pragma unroll
        for (int i = 0; i < 4; i++)
            CP16(s2u(st + dBase + i * 32 * SROW),
                 A + (size_t)(row0 + r0 + i * 32) * FDIM + k0 + ch * 8);
#pragma unroll
        for (int i = 0; i < 2; i++)
            CP16(s2u(st + dBase + (128 + i * 32) * SROW),
                 B + (size_t)(col0 + r0 + i * 32) * FDIM + k0 + ch * 8);
        CPCOMMIT();
    }

    for (int it = 0; it < NIT2; it++) {
        CPWAIT(STAGES2 - 2);
        __syncthreads();

        const int nxt = it + STAGES2 - 1;
        if (nxt < NIT2) {
            __nv_bfloat16* st = sm2 + (nxt % STAGES2) * S2_STAGE_E;
            const __nv_bfloat16* A = (nxt < HALF2N) ? g_a : g_w;
            const __nv_bfloat16* B = (nxt < HALF2N) ? g_v : g_c;
            const int k0 = (nxt & (HALF2N - 1)) * 32;
#pragma unroll
            for (int i = 0; i < 4; i++)
                CP16(s2u(st + dBase + i * 32 * SROW),
                     A + (size_t)(row0 + r0 + i * 32) * FDIM + k0 + ch * 8);
#pragma unroll
            for (int i = 0; i < 2; i++)
                CP16(s2u(st + dBase + (128 + i * 32) * SROW),
                     B + (size_t)(col0 + r0 + i * 32) * FDIM + k0 + ch * 8);
        }
        CPCOMMIT();

        const uint32_t su = sb + (it % STAGES2) * S2_STAGE_B;
        const uint32_t aBase = su + 2 * (wm * 64 * SROW + aOff);
        const uint32_t bBase = su + 2 * ((128 + wn * 32) * SROW + bOff);

        uint32_t af[2][4][4], bf[2][4][2];
#pragma unroll
        for (int mi = 0; mi < 4; mi++)
            ldsm4(af[0][mi][0], af[0][mi][1], af[0][mi][2], af[0][mi][3],
                  aBase + 2 * (mi * 16 * SROW));
#pragma unroll
        for (int nb = 0; nb < 2; nb++)
            ldsm4(bf[0][2 * nb][0], bf[0][2 * nb][1], bf[0][2 * nb + 1][0], bf[0][2 * nb + 1][1],
                  bBase + 2 * (nb * 16 * SROW));

#pragma unroll
        for (int ks = 0; ks < 2; ks++) {
            const int cur = ks & 1, nx2 = cur ^ 1;
            if (ks < 1) {
                const int kk = 16;
#pragma unroll
                for (int mi = 0; mi < 4; mi++)
                    ldsm4(af[nx2][mi][0], af[nx2][mi][1], af[nx2][mi][2], af[nx2][mi][3],
                          aBase + 2 * (mi * 16 * SROW + kk));
#pragma unroll
                for (int nb = 0; nb < 2; nb++)
                    ldsm4(bf[nx2][2 * nb][0], bf[nx2][2 * nb][1],
                          bf[nx2][2 * nb + 1][0], bf[nx2][2 * nb + 1][1],
                          bBase + 2 * (nb * 16 * SROW + kk));
            }
#pragma unroll
            for (int mi = 0; mi < 4; mi++)
#pragma unroll
                for (int ni = 0; ni < 4; ni++)
                    mma_bf16(acc[mi][ni], af[cur][mi], bf[cur][ni]);
        }
    }

#pragma unroll
    for (int mi = 0; mi < 4; mi++)
#pragma unroll
        for (int ni = 0; ni < 4; ni++) {
            const int rr = row0 + wm * 64 + mi * 16 + g;
            const int cc = col0 + wn * 32 + ni * 8 + tg * 2;
#pragma unroll
            for (int h = 0; h < 2; h++) {
                float2 o = { acc[mi][ni][h * 2 + 0], acc[mi][ni][h * 2 + 1] };
                *(float2*)&Out[(size_t)(rr + h * 8) * PDIM + cc] = o;
            }
        }
}

// ---------------- launch ----------------
extern "C" void kernel_launch(void* const* d_in, const int* in_sizes, int n_in,
                              void* d_out, int out_size)
{
    const float* x     = (const float*)d_in[0];
    const float* feat  = (const float*)d_in[1];
    const float* proto = (const float*)d_in[2];
    const float* alpha = (const float*)d_in[3];
    const float* beta  = (const float*)d_in[4];
    const float* theta = (const float*)d_in[5];
    float* out = (float*)d_out;

    static bool attr_done = false;
    if (!attr_done) {
        cudaFuncSetAttribute(s1_kernel, cudaFuncAttributeMaxDynamicSharedMemorySize, S1_SMEM);
        cudaFuncSetAttribute(s2_kernel, cudaFuncAttributeMaxDynamicSharedMemorySize, S2_SMEM);
        attr_done = true;
    }

    const int ntot = (BDIM + FDIM + PDIM) * IDIM / 4;
    cvt_all<<<(ntot + 255) / 256, 256>>>((const float4*)x, (const float4*)feat,
                                         (const float4*)proto);
    s1_kernel<<<dim3(FDIM / 128, (BDIM + PDIM) / 128), 256, S1_SMEM>>>(alpha, beta, theta);
    s2_kernel<<<dim3(PDIM / 64, BDIM / 128), 128, S2_SMEM>>>(out);
}

// round 9
// speedup vs baseline: 8.9537x; 1.0643x over previous
#include <cuda_runtime.h>
#include <cuda_fp16.h>
#include <cuda_bf16.h>
#include <stdint.h>

#define BDIM 4096
#define PDIM 512
#define IDIM 1024
#define FDIM 2048

// ---------------- scratch (device globals; allocation-free rule) ----------------
__device__ __align__(128) __half g_xh[(size_t)BDIM * IDIM];
__device__ __align__(128) __half g_fh[(size_t)FDIM * IDIM];
__device__ __align__(128) __half g_ph[(size_t)PDIM * IDIM];
__device__ __align__(128) __nv_bfloat16 g_a[(size_t)BDIM * FDIM];  // xf*relu(xf)
__device__ __align__(128) __nv_bfloat16 g_w[(size_t)BDIM * FDIM];  // -beta*(1-relu(xf))
__device__ __align__(128) __nv_bfloat16 g_v[(size_t)PDIM * FDIM];  // theta*c - alpha*(1-relu(pf))
__device__ __align__(128) __nv_bfloat16 g_c[(size_t)PDIM * FDIM];  // pf*relu(pf)

// ---------------- helpers ----------------
__device__ __forceinline__ uint32_t s2u(const void* p) {
    uint32_t a;
    asm("{ .reg .u64 t; cvta.to.shared.u64 t, %1; cvt.u32.u64 %0, t; }" : "=r"(a) : "l"(p));
    return a;
}

#define CP16(dst, src) \
    asm volatile("cp.async.cg.shared.global [%0], [%1], 16;" :: "r"(dst), "l"(src))
#define CPCOMMIT() asm volatile("cp.async.commit_group;")
#define CPWAIT(n)  asm volatile("cp.async.wait_group %0;" :: "n"(n))

__device__ __forceinline__ void ldsm4(uint32_t& r0, uint32_t& r1, uint32_t& r2, uint32_t& r3,
                                      uint32_t addr) {
    asm volatile("ldmatrix.sync.aligned.m8n8.x4.shared.b16 {%0,%1,%2,%3}, [%4];"
                 : "=r"(r0), "=r"(r1), "=r"(r2), "=r"(r3) : "r"(addr));
}

__device__ __forceinline__ void mma_f16(float c[4], const uint32_t a[4], const uint32_t b[2]) {
    asm volatile(
        "mma.sync.aligned.m16n8k16.row.col.f32.f16.f16.f32 "
        "{%0,%1,%2,%3}, {%4,%5,%6,%7}, {%8,%9}, {%0,%1,%2,%3};"
        : "+f"(c[0]), "+f"(c[1]), "+f"(c[2]), "+f"(c[3])
        : "r"(a[0]), "r"(a[1]), "r"(a[2]), "r"(a[3]), "r"(b[0]), "r"(b[1]));
}

__device__ __forceinline__ void mma_bf16(float c[4], const uint32_t a[4], const uint32_t b[2]) {
    asm volatile(
        "mma.sync.aligned.m16n8k16.row.col.f32.bf16.bf16.f32 "
        "{%0,%1,%2,%3}, {%4,%5,%6,%7}, {%8,%9}, {%0,%1,%2,%3};"
        : "+f"(c[0]), "+f"(c[1]), "+f"(c[2]), "+f"(c[3])
        : "r"(a[0]), "r"(a[1]), "r"(a[2]), "r"(a[3]), "r"(b[0]), "r"(b[1]));
}

// ---------------- merged fp32 -> fp16 conversion (one launch) ----------------
__global__ void cvt_all(const float4* __restrict__ x, const float4* __restrict__ f,
                        const float4* __restrict__ p)
{
    const int nx = BDIM * IDIM / 4, nf = FDIM * IDIM / 4, np = PDIM * IDIM / 4;
    int i = blockIdx.x * blockDim.x + threadIdx.x;
    const float4* src; uint2* dst; int j;
    if (i < nx)                { src = x; dst = (uint2*)g_xh; j = i; }
    else if (i < nx + nf)      { src = f; dst = (uint2*)g_fh; j = i - nx; }
    else if (i < nx + nf + np) { src = p; dst = (uint2*)g_ph; j = i - nx - nf; }
    else return;
    float4 v = src[j];
    __half2 h0 = __floats2half2_rn(v.x, v.y);
    __half2 h1 = __floats2half2_rn(v.z, v.w);
    uint2 o; o.x = *(uint32_t*)&h0; o.y = *(uint32_t*)&h1;
    dst[j] = o;
}

// =================================================================
// Stage 1 (fp16 m16n8k16): Y = In @ Feat^T, merged x/proto grids.
// CTA 128x128, 128 threads, 4 warps (2x2), warp tile 64x64,
// k-tile 32, 4-stage cp.async, fragment double-buffering.
//   x-side  (rb<32): g_a = y*p,                    g_w = -beta*(1-p)
//   p-side (rb>=32): g_v = theta*y*p - alpha*(1-p), g_c = y*p
// =================================================================
#define SROW 40                            // 32 data + 8 pad halfs (80 B row)
#define S1_STAGE_E (256 * SROW)
#define S1_STAGE_B (S1_STAGE_E * 2)        // 20480 bytes
#define STAGES1 4
#define S1_SMEM (STAGES1 * S1_STAGE_B)     // 81920 bytes

__global__ __launch_bounds__(128, 2)
void s1_kernel(const float* __restrict__ alpha, const float* __restrict__ beta,
               const float* __restrict__ theta)
{
    extern __shared__ __half sm1[];
    const uint32_t sb = s2u(sm1);
    const int tid = threadIdx.x;
    const int wid = tid >> 5, lid = tid & 31;
    const int g = lid >> 2, tg = lid & 3;
    const int wm = wid >> 1, wn = wid & 1;              // 2 x 2 warps, 64x64 tile
    const int rb = blockIdx.y;
    const bool isX = rb < (BDIM / 128);
    const int row0 = (isX ? rb : rb - BDIM / 128) * 128;
    const int col0 = blockIdx.x * 128;

    const __half* In = isX ? g_xh : g_ph;
    __nv_bfloat16* out1 = isX ? g_a : g_v;
    __nv_bfloat16* out2 = isX ? g_w : g_c;

    // loader: 1024 cp16 per stage / 128 threads = 8 each (4 A + 4 B rows)
    const int r0 = tid >> 2, ch = tid & 3;              // r0: 0..31, ch: 0..3
    const __half* srcA = In   + (size_t)(row0 + r0) * IDIM + ch * 8;
    const __half* srcB = g_fh + (size_t)(col0 + r0) * IDIM + ch * 8;
    const int dBase = r0 * SROW + ch * 8;

    const int aOff = ((lid & 7) + ((lid >> 3) & 1) * 8) * SROW + (lid >> 4) * 8;
    const int bOff = ((lid & 7) + (lid >> 4) * 8) * SROW + ((lid >> 3) & 1) * 8;

    float acc[4][8][4];
#pragma unroll
    for (int mi = 0; mi < 4; mi++)
#pragma unroll
        for (int ni = 0; ni < 8; ni++)
#pragma unroll
            for (int j = 0; j < 4; j++) acc[mi][ni][j] = 0.f;

    const int NIT = IDIM / 32;   // 32

#pragma unroll
    for (int s = 0; s < STAGES1 - 1; s++) {
        __half* st = sm1 + s * S1_STAGE_E;
        const int k0 = s * 32;
#pragma unroll
        for (int i = 0; i < 4; i++) {
            CP16(s2u(st + dBase + i * 32 * SROW), srcA + (size_t)(i * 32) * IDIM + k0);
            CP16(s2u(st + dBase + (128 + i * 32) * SROW), srcB + (size_t)(i * 32) * IDIM + k0);
        }
        CPCOMMIT();
    }

    for (int it = 0; it < NIT; it++) {
        CPWAIT(STAGES1 - 2);
        __syncthreads();

        const int nxt = it + STAGES1 - 1;
        if (nxt < NIT) {
            __half* st = sm1 + (nxt % STAGES1) * S1_STAGE_E;
            const int k0 = nxt * 32;
#pragma unroll
            for (int i = 0; i < 4; i++) {
                CP16(s2u(st + dBase + i * 32 * SROW), srcA + (size_t)(i * 32) * IDIM + k0);
                CP16(s2u(st + dBase + (128 + i * 32) * SROW), srcB + (size_t)(i * 32) * IDIM + k0);
            }
        }
        CPCOMMIT();

        const uint32_t su = sb + (it % STAGES1) * S1_STAGE_B;
        const uint32_t aBase = su + 2 * (wm * 64 * SROW + aOff);
        const uint32_t bBase = su + 2 * ((128 + wn * 64) * SROW + bOff);

        uint32_t af[2][4][4], bf[2][8][2];
#pragma unroll
        for (int mi = 0; mi < 4; mi++)
            ldsm4(af[0][mi][0], af[0][mi][1], af[0][mi][2], af[0][mi][3],
                  aBase + 2 * (mi * 16 * SROW));
#pragma unroll
        for (int nb = 0; nb < 4; nb++)
            ldsm4(bf[0][2 * nb][0], bf[0][2 * nb][1], bf[0][2 * nb + 1][0], bf[0][2 * nb + 1][1],
                  bBase + 2 * (nb * 16 * SROW));

#pragma unroll
        for (int ks = 0; ks < 2; ks++) {
            const int cur = ks & 1, nx2 = cur ^ 1;
            if (ks < 1) {
                const int kk = 16;
#pragma unroll
                for (int mi = 0; mi < 4; mi++)
                    ldsm4(af[nx2][mi][0], af[nx2][mi][1], af[nx2][mi][2], af[nx2][mi][3],
                          aBase + 2 * (mi * 16 * SROW + kk));
#pragma unroll
                for (int nb = 0; nb < 4; nb++)
                    ldsm4(bf[nx2][2 * nb][0], bf[nx2][2 * nb][1],
                          bf[nx2][2 * nb + 1][0], bf[nx2][2 * nb + 1][1],
                          bBase + 2 * (nb * 16 * SROW + kk));
            }
#pragma unroll
            for (int mi = 0; mi < 4; mi++)
#pragma unroll
                for (int ni = 0; ni < 8; ni++)
                    mma_f16(acc[mi][ni], af[cur][mi], bf[cur][ni]);
        }
    }

    const float al = __ldg(alpha);
    const float be = __ldg(beta);
    const float th = __ldg(theta);

#pragma unroll
    for (int mi = 0; mi < 4; mi++)
#pragma unroll
        for (int ni = 0; ni < 8; ni++) {
            const int rr = row0 + wm * 64 + mi * 16 + g;
            const int cc = col0 + wn * 64 + ni * 8 + tg * 2;
#pragma unroll
            for (int h = 0; h < 2; h++) {
                const float y0 = acc[mi][ni][h * 2 + 0];
                const float y1 = acc[mi][ni][h * 2 + 1];
                const float p0 = fmaxf(y0, 0.f), p1 = fmaxf(y1, 0.f);
                const float yp0 = y0 * p0, yp1 = y1 * p1;
                const float iv0 = 1.f - p0, iv1 = 1.f - p1;
                float o1a, o1b, o2a, o2b;
                if (isX) { o1a = yp0;                  o1b = yp1;
                           o2a = -be * iv0;            o2b = -be * iv1; }
                else     { o1a = th * yp0 - al * iv0;  o1b = th * yp1 - al * iv1;
                           o2a = yp0;                  o2b = yp1; }
                const size_t off = (size_t)(rr + h * 8) * FDIM + cc;
                *(__nv_bfloat162*)&out1[off] = __floats2bfloat162_rn(o1a, o1b);
                *(__nv_bfloat162*)&out2[off] = __floats2bfloat162_rn(o2a, o2b);
            }
        }
}

// =================================================================
// Stage 2 (bf16 m16n8k16): out = a @ v^T + w @ c^T (two k-phases over F)
// CTA 128x64, k-tile 32, 3-stage cp.async, 4 warps (2x2), warp 64x32,
// fragment double-buffering across the 2 k16 slices.
// =================================================================
#define STAGES2 3
#define S2_STAGE_E (192 * SROW)            // 128 A rows + 64 B rows
#define S2_STAGE_B (S2_STAGE_E * 2)        // 15360 bytes
#define S2_SMEM    (STAGES2 * S2_STAGE_B)  // 46080 bytes
#define NIT2 (2 * FDIM / 32)               // 128
#define HALF2N (FDIM / 32)                 // 64

__global__ __launch_bounds__(128, 4)
void s2_kernel(float* __restrict__ Out)
{
    extern __shared__ __nv_bfloat16 sm2[];
    const uint32_t sb = s2u(sm2);
    const int tid = threadIdx.x;
    const int wid = tid >> 5, lid = tid & 31;
    const int g = lid >> 2, tg = lid & 3;
    const int wm = wid >> 1, wn = wid & 1;              // 2 x 2 warps, warp 64x32
    const int row0 = blockIdx.y * 128;
    const int col0 = blockIdx.x * 64;

    const int r0 = tid >> 2, ch = tid & 3;
    const int dBase = r0 * SROW + ch * 8;

    const int aOff = ((lid & 7) + ((lid >> 3) & 1) * 8) * SROW + (lid >> 4) * 8;
    const int bOff = ((lid & 7) + (lid >> 4) * 8) * SROW + ((lid >> 3) & 1) * 8;

    float acc[4][4][4];
#pragma unroll
    for (int mi = 0; mi < 4; mi++)
#pragma unroll
        for (int ni = 0; ni < 4; ni++)
#pragma unroll
            for (int j = 0; j < 4; j++) acc[mi][ni][j] = 0.f;

#pragma unroll
    for (int s = 0; s < STAGES2 - 1; s++) {
        __nv_bfloat16* st = sm2 + s * S2_STAGE_E;
        const __nv_bfloat16* A = (s < HALF2N) ? g_a : g_w;
        const __nv_bfloat16* B = (s < HALF2N) ? g_v : g_c;
        const int k0 = (s & (HALF2N - 1)) * 32;
#pragma unroll
        for (int i = 0; i < 4; i++)
            CP16(s2u(st + dBase + i * 32 * SROW),
                 A + (size_t)(row0 + r0 + i * 32) * FDIM + k0 + ch * 8);
#pragma unroll
        for (int i = 0; i < 2; i++)
            CP16(s2u(st + dBase + (128 + i * 32) * SROW),
                 B + (size_t)(col0 + r0 + i * 32) * FDIM + k0 + ch * 8);
        CPCOMMIT();
    }

    for (int it = 0; it < NIT2; it++) {
        CPWAIT(STAGES2 - 2);
        __syncthreads();

        const int nxt = it + STAGES2 - 1;
        if (nxt < NIT2) {
            __nv_bfloat16* st = sm2 + (nxt % STAGES2) * S2_STAGE_E;
            const __nv_bfloat16* A = (nxt < HALF2N) ? g_a : g_w;
            const __nv_bfloat16* B = (nxt < HALF2N) ? g_v : g_c;
            const int k0 = (nxt & (HALF2N - 1)) * 32;
#pragma unroll
            for (int i = 0; i < 4; i++)
                CP16(s2u(st + dBase + i * 32 * SROW),
                     A + (size_t)(row0 + r0 + i * 32) * FDIM + k0 + ch * 8);
#pragma unroll
            for (int i = 0; i < 2; i++)
                CP16(s2u(st + dBase + (128 + i * 32) * SROW),
                     B + (size_t)(col0 + r0 + i * 32) * FDIM + k0 + ch * 8);
        }
        CPCOMMIT();

        const uint32_t su = sb + (it % STAGES2) * S2_STAGE_B;
        const uint32_t aBase = su + 2 * (wm * 64 * SROW + aOff);
        const uint32_t bBase = su + 2 * ((128 + wn * 32) * SROW + bOff);

        uint32_t af[2][4][4], bf[2][4][2];
#pragma unroll
        for (int mi = 0; mi < 4; mi++)
            ldsm4(af[0][mi][0], af[0][mi][1], af[0][mi][2], af[0][mi][3],
                  aBase + 2 * (mi * 16 * SROW));
#pragma unroll
        for (int nb = 0; nb < 2; nb++)
            ldsm4(bf[0][2 * nb][0], bf[0][2 * nb][1], bf[0][2 * nb + 1][0], bf[0][2 * nb + 1][1],
                  bBase + 2 * (nb * 16 * SROW));

#pragma unroll
        for (int ks = 0; ks < 2; ks++) {
            const int cur = ks & 1, nx2 = cur ^ 1;
            if (ks < 1) {
                const int kk = 16;
#pragma unroll
                for (int mi = 0; mi < 4; mi++)
                    ldsm4(af[nx2][mi][0], af[nx2][mi][1], af[nx2][mi][2], af[nx2][mi][3],
                          aBase + 2 * (mi * 16 * SROW + kk));
#pragma unroll
                for (int nb = 0; nb < 2; nb++)
                    ldsm4(bf[nx2][2 * nb][0], bf[nx2][2 * nb][1],
                          bf[nx2][2 * nb + 1][0], bf[nx2][2 * nb + 1][1],
                          bBase + 2 * (nb * 16 * SROW + kk));
            }
#pragma unroll
            for (int mi = 0; mi < 4; mi++)
#pragma unroll
                for (int ni = 0; ni < 4; ni++)
                    mma_bf16(acc[mi][ni], af[cur][mi], bf[cur][ni]);
        }
    }

#pragma unroll
    for (int mi = 0; mi < 4; mi++)
#pragma unroll
        for (int ni = 0; ni < 4; ni++) {
            const int rr = row0 + wm * 64 + mi * 16 + g;
            const int cc = col0 + wn * 32 + ni * 8 + tg * 2;
#pragma unroll
            for (int h = 0; h < 2; h++) {
                float2 o = { acc[mi][ni][h * 2 + 0], acc[mi][ni][h * 2 + 1] };
                *(float2*)&Out[(size_t)(rr + h * 8) * PDIM + cc] = o;
            }
        }
}

// ---------------- launch ----------------
extern "C" void kernel_launch(void* const* d_in, const int* in_sizes, int n_in,
                              void* d_out, int out_size)
{
    const float* x     = (const float*)d_in[0];
    const float* feat  = (const float*)d_in[1];
    const float* proto = (const float*)d_in[2];
    const float* alpha = (const float*)d_in[3];
    const float* beta  = (const float*)d_in[4];
    const float* theta = (const float*)d_in[5];
    float* out = (float*)d_out;

    static bool attr_done = false;
    if (!attr_done) {
        cudaFuncSetAttribute(s1_kernel, cudaFuncAttributeMaxDynamicSharedMemorySize, S1_SMEM);
        cudaFuncSetAttribute(s2_kernel, cudaFuncAttributeMaxDynamicSharedMemorySize, S2_SMEM);
        attr_done = true;
    }

    const int ntot = (BDIM + FDIM + PDIM) * IDIM / 4;
    cvt_all<<<(ntot + 255) / 256, 256>>>((const float4*)x, (const float4*)feat,
                                         (const float4*)proto);
    s1_kernel<<<dim3(FDIM / 128, (BDIM + PDIM) / 128), 128, S1_SMEM>>>(alpha, beta, theta);
    s2_kernel<<<dim3(PDIM / 64, BDIM / 128), 128, S2_SMEM>>>(out);
}